// round 1
// baseline (speedup 1.0000x reference)
#include <cuda_runtime.h>
#include <math.h>

// LSTMCell: gates = incoming @ W^T + old_h @ U^T + b   (B=4096, I=H=1024, 4 gates)
//           i,o,f = sigmoid, c~ = tanh; new_c = f*old_c + i*c~; new_h = o*tanh(new_c)
// Inputs (metadata order): incoming, old_h, old_c, then per gate j in [i,o,f,c]:
//   w_j [H,I], b_j [H], u_j [H,H]
// Output: new_h (B*H floats) followed by new_c (B*H floats).

#define BATCH 4096
#define HID   1024
#define GATES4 4096   // 4*HID

#define BM 128
#define BN 128
#define BK 8
#define TM 8
#define TN 8
#define THREADS 256

// Scratch for the gate pre-activations [BATCH, 4H] (64 MB, static device array).
__device__ float g_gates[(size_t)BATCH * GATES4];

struct GateParams {
    const float* w[4];
    const float* u[4];
    const float* b[4];
};

__global__ __launch_bounds__(THREADS)
void gemm_gates_kernel(const float* __restrict__ X,   // incoming [B, I]
                       const float* __restrict__ Hs,  // old_h    [B, H]
                       GateParams gp)
{
    __shared__ float As[BK][BM];
    __shared__ float Bs[BK][BN];

    const int t      = threadIdx.x;
    const int m0     = blockIdx.y * BM;          // batch-tile origin
    const int ntile  = blockIdx.x;               // 0..31 over 4H
    const int gate   = ntile >> 3;               // 8 tiles of 128 per gate
    const int n0     = (ntile & 7) * BN;         // offset inside gate's 1024 cols

    const int tx = t & 15;                       // 16 col groups
    const int ty = t >> 4;                       // 16 row groups

    // Global-load indexing: 128 rows x 8 cols per tile; 2 float4 per row.
    const int lrow = t >> 1;                     // 0..127
    const int lcol = (t & 1) * 4;                // 0 or 4

    float acc[TM][TN];
    #pragma unroll
    for (int i = 0; i < TM; i++)
        #pragma unroll
        for (int j = 0; j < TN; j++)
            acc[i][j] = 0.0f;

    #pragma unroll
    for (int seg = 0; seg < 2; seg++) {
        const float* A  = (seg == 0) ? X : Hs;
        const float* Wp = (seg == 0) ? gp.w[gate] : gp.u[gate];

        for (int k0 = 0; k0 < 1024; k0 += BK) {
            float4 av = *reinterpret_cast<const float4*>(A  + (size_t)(m0 + lrow) * 1024 + k0 + lcol);
            float4 bv = *reinterpret_cast<const float4*>(Wp + (size_t)(n0 + lrow) * 1024 + k0 + lcol);

            __syncthreads();   // previous compute done before overwriting smem
            As[lcol + 0][lrow] = av.x;
            As[lcol + 1][lrow] = av.y;
            As[lcol + 2][lrow] = av.z;
            As[lcol + 3][lrow] = av.w;
            Bs[lcol + 0][lrow] = bv.x;
            Bs[lcol + 1][lrow] = bv.y;
            Bs[lcol + 2][lrow] = bv.z;
            Bs[lcol + 3][lrow] = bv.w;
            __syncthreads();

            #pragma unroll
            for (int kk = 0; kk < BK; kk++) {
                float4 a0 = *reinterpret_cast<const float4*>(&As[kk][ty * TM]);
                float4 a1 = *reinterpret_cast<const float4*>(&As[kk][ty * TM + 4]);
                float4 b0 = *reinterpret_cast<const float4*>(&Bs[kk][tx * TN]);
                float4 b1 = *reinterpret_cast<const float4*>(&Bs[kk][tx * TN + 4]);
                float a[TM] = {a0.x, a0.y, a0.z, a0.w, a1.x, a1.y, a1.z, a1.w};
                float bb[TN] = {b0.x, b0.y, b0.z, b0.w, b1.x, b1.y, b1.z, b1.w};
                #pragma unroll
                for (int i = 0; i < TM; i++)
                    #pragma unroll
                    for (int j = 0; j < TN; j++)
                        acc[i][j] = fmaf(a[i], bb[j], acc[i][j]);
            }
        }
    }

    // Epilogue: add bias, store to gates scratch [B, 4H].
    const float* bias = gp.b[gate] + n0 + tx * TN;
    float bv[TN];
    #pragma unroll
    for (int j = 0; j < TN; j++) bv[j] = bias[j];

    const int ncol = gate * 1024 + n0 + tx * TN;   // global column in [0,4096)
    #pragma unroll
    for (int i = 0; i < TM; i++) {
        const int row = m0 + ty * TM + i;
        float* out = g_gates + (size_t)row * GATES4 + ncol;
        float4 v0 = make_float4(acc[i][0] + bv[0], acc[i][1] + bv[1],
                                acc[i][2] + bv[2], acc[i][3] + bv[3]);
        float4 v1 = make_float4(acc[i][4] + bv[4], acc[i][5] + bv[5],
                                acc[i][6] + bv[6], acc[i][7] + bv[7]);
        *reinterpret_cast<float4*>(out)     = v0;
        *reinterpret_cast<float4*>(out + 4) = v1;
    }
}

__device__ __forceinline__ float sigmoidf_(float x) {
    return 1.0f / (1.0f + expf(-x));
}

__global__ __launch_bounds__(256)
void lstm_elem_kernel(const float* __restrict__ old_c,
                      float* __restrict__ new_h,
                      float* __restrict__ new_c)
{
    int idx = blockIdx.x * blockDim.x + threadIdx.x;     // 0 .. B*H-1
    int b = idx >> 10;
    int h = idx & 1023;
    const float* grow = g_gates + (size_t)b * GATES4;
    float gi = grow[h];
    float go = grow[1024 + h];
    float gf = grow[2048 + h];
    float gc = grow[3072 + h];

    float i = sigmoidf_(gi);
    float o = sigmoidf_(go);
    float f = sigmoidf_(gf);
    float ct = tanhf(gc);
    float nc = f * old_c[idx] + i * ct;
    new_h[idx] = o * tanhf(nc);
    new_c[idx] = nc;
}

extern "C" void kernel_launch(void* const* d_in, const int* in_sizes, int n_in,
                              void* d_out, int out_size)
{
    const float* incoming = (const float*)d_in[0];
    const float* old_h    = (const float*)d_in[1];
    const float* old_c    = (const float*)d_in[2];

    GateParams gp;
    // gate order: i, o, f, c ; per gate the inputs are (w, b, u)
    gp.w[0] = (const float*)d_in[3];  gp.b[0] = (const float*)d_in[4];  gp.u[0] = (const float*)d_in[5];
    gp.w[1] = (const float*)d_in[6];  gp.b[1] = (const float*)d_in[7];  gp.u[1] = (const float*)d_in[8];
    gp.w[2] = (const float*)d_in[9];  gp.b[2] = (const float*)d_in[10]; gp.u[2] = (const float*)d_in[11];
    gp.w[3] = (const float*)d_in[12]; gp.b[3] = (const float*)d_in[13]; gp.u[3] = (const float*)d_in[14];

    float* out_h = (float*)d_out;                          // [B*H]
    float* out_c = out_h + (size_t)BATCH * HID;            // [B*H]

    dim3 grid(GATES4 / BN, BATCH / BM);                    // 32 x 32
    gemm_gates_kernel<<<grid, THREADS>>>(incoming, old_h, gp);

    int total = BATCH * HID;
    lstm_elem_kernel<<<total / 256, 256>>>(old_c, out_h, out_c);
}

// round 3
// speedup vs baseline: 2.3390x; 2.3390x over previous
#include <cuda_runtime.h>
#include <cuda_bf16.h>
#include <cstdint>

// LSTMCell fused via mma.sync (HMMA) bf16 hi/lo-split GEMM, fp32 accumulate.
// gates = X@W^T + H@U^T + b ; i,o,f=sigmoid, c~=tanh; new_c=f*oc+i*c~; new_h=o*tanh(new_c)
// B=4096, I=H=1024. CTA tile: M=128 x N=128 (N = 32 h-values x 4 gates).
// K = 2048 (X segment then H segment), chunks of 32, double-buffered smem.

#define HID     1024
#define BATCHSZ 4096
#define KCH     32
#define NCHUNK  64          // 2048 / 32
#define THREADS 256

// smem: per stage, A tile 128 rows x 128B (32 bf16 hi | 32 bf16 lo), B same.
#define A_STAGE_BYTES (128*128)
#define STAGE_BYTES   (2*A_STAGE_BYTES)          // A + B = 32 KB
#define CSM_BYTES     (128*129*4)                // epilogue transpose buffer
#define DYN_BYTES     (2*STAGE_BYTES + 1024 > CSM_BYTES + 1024 ? 2*STAGE_BYTES + 1024 : CSM_BYTES + 1024)

struct GateParams { const float* w[4]; const float* u[4]; const float* b[4]; };

static __device__ __forceinline__ uint32_t smem_u32(const void* p) {
    uint32_t a;
    asm("{ .reg .u64 t; cvta.to.shared.u64 t, %1; cvt.u32.u64 %0, t; }" : "=r"(a) : "l"(p));
    return a;
}
static __device__ __forceinline__ uint32_t sw128(uint32_t off) {
    return off ^ ((off >> 3) & 0x70);
}
static __device__ __forceinline__ void ldsm_x4(uint32_t* r, uint32_t addr) {
    asm volatile("ldmatrix.sync.aligned.m8n8.x4.shared.b16 {%0,%1,%2,%3}, [%4];"
        : "=r"(r[0]), "=r"(r[1]), "=r"(r[2]), "=r"(r[3]) : "r"(addr));
}
static __device__ __forceinline__ void mma_bf16(float* c, const uint32_t* a, const uint32_t* b) {
    asm volatile("mma.sync.aligned.m16n8k16.row.col.f32.bf16.bf16.f32 "
        "{%0,%1,%2,%3}, {%4,%5,%6,%7}, {%8,%9}, {%0,%1,%2,%3};"
        : "+f"(c[0]), "+f"(c[1]), "+f"(c[2]), "+f"(c[3])
        : "r"(a[0]), "r"(a[1]), "r"(a[2]), "r"(a[3]), "r"(b[0]), "r"(b[1]));
}

// fp32 float4 -> packed bf16x2 hi words (h01,h23) and lo words (l01,l23)
static __device__ __forceinline__ void split4(float4 v, uint32_t& h01, uint32_t& h23,
                                              uint32_t& l01, uint32_t& l23) {
    __nv_bfloat162 H01 = __floats2bfloat162_rn(v.x, v.y);
    __nv_bfloat162 H23 = __floats2bfloat162_rn(v.z, v.w);
    float2 f01 = __bfloat1622float2(H01);
    float2 f23 = __bfloat1622float2(H23);
    __nv_bfloat162 L01 = __floats2bfloat162_rn(v.x - f01.x, v.y - f01.y);
    __nv_bfloat162 L23 = __floats2bfloat162_rn(v.z - f23.x, v.w - f23.y);
    h01 = *reinterpret_cast<uint32_t*>(&H01);
    h23 = *reinterpret_cast<uint32_t*>(&H23);
    l01 = *reinterpret_cast<uint32_t*>(&L01);
    l23 = *reinterpret_cast<uint32_t*>(&L23);
}

static __device__ __forceinline__ float fast_sig(float x) {
    return 1.0f / (1.0f + __expf(-x));
}
static __device__ __forceinline__ float fast_tanh(float x) {
    float e = __expf(2.0f * x);
    return 1.0f - 2.0f / (e + 1.0f);
}

__global__ __launch_bounds__(THREADS, 1)
void lstm_hmma_kernel(const float* __restrict__ X, const float* __restrict__ Hst,
                      const float* __restrict__ oldc, GateParams gp,
                      float* __restrict__ outh, float* __restrict__ outc)
{
    extern __shared__ char dyn_raw[];
    char* dyn = (char*)(((uintptr_t)dyn_raw + 1023) & ~(uintptr_t)1023);
    __shared__ float bias_sm[128];

    const int tid  = threadIdx.x;
    const int lane = tid & 31;
    const int warp = tid >> 5;
    const int wm   = warp >> 2;          // 0..1 : 64 m-rows each
    const int wn   = warp & 3;           // 0..3 : 32 n-cols each
    const int h0   = blockIdx.x * 32;    // 32 h-tiles
    const int m0   = blockIdx.y * 128;   // 32 m-tiles

    if (tid < 128) bias_sm[tid] = gp.b[tid >> 5][h0 + (tid & 31)];

    // ---- global load mapping: thread t -> colf4 = t&7 (16B within 128B row),
    //      rowgrp = t>>3 (0..31); loads rows rowgrp + 32*i, i=0..3.
    const int colf4  = tid & 7;
    const int rowgrp = tid >> 3;
    const float* aBase[2] = {
        X   + (size_t)(m0 + rowgrp) * 1024 + colf4 * 4,
        Hst + (size_t)(m0 + rowgrp) * 1024 + colf4 * 4
    };
    const float* bBase[2][4];
    #pragma unroll
    for (int g = 0; g < 4; g++) {
        bBase[0][g] = gp.w[g] + (size_t)(h0 + rowgrp) * 1024 + colf4 * 4;
        bBase[1][g] = gp.u[g] + (size_t)(h0 + rowgrp) * 1024 + colf4 * 4;
    }

    const uint32_t sm_base = smem_u32(dyn);
    // per-stage tile bases (byte offsets into dyn): A at s*32K, B at s*32K+16K
    // smem fragment address components (constant per thread):
    const uint32_t arow_b = (uint32_t)((wm * 64 + (lane & 15)) * 128) + ((lane >> 4) << 4);
    const uint32_t brow_b = (uint32_t)((wn * 32 + ((lane >> 4) << 3) + (lane & 7)) * 128) + (((lane >> 3) & 1) << 4);

    float acc[4][4][4];
    #pragma unroll
    for (int mt = 0; mt < 4; mt++)
        #pragma unroll
        for (int nt = 0; nt < 4; nt++)
            #pragma unroll
            for (int q = 0; q < 4; q++) acc[mt][nt][q] = 0.0f;

    float4 av[4], bv[4];

    // ---- prologue: load + store chunk 0
    {
        const float* ap = aBase[0];
        #pragma unroll
        for (int i = 0; i < 4; i++) av[i] = *reinterpret_cast<const float4*>(ap + (size_t)i * 32 * 1024);
        #pragma unroll
        for (int i = 0; i < 4; i++) bv[i] = *reinterpret_cast<const float4*>(bBase[0][i]);

        char* sA = dyn;
        char* sB = dyn + A_STAGE_BYTES;
        #pragma unroll
        for (int i = 0; i < 4; i++) {
            uint32_t h01, h23, l01, l23;
            split4(av[i], h01, h23, l01, l23);
            uint32_t off = (uint32_t)((rowgrp + 32 * i) * 128 + colf4 * 8);
            *reinterpret_cast<uint2*>(sA + sw128(off))      = make_uint2(h01, h23);
            *reinterpret_cast<uint2*>(sA + sw128(off + 64)) = make_uint2(l01, l23);
            split4(bv[i], h01, h23, l01, l23);
            *reinterpret_cast<uint2*>(sB + sw128(off))      = make_uint2(h01, h23);
            *reinterpret_cast<uint2*>(sB + sw128(off + 64)) = make_uint2(l01, l23);
        }
    }
    __syncthreads();

    for (int c = 0; c < NCHUNK; c++) {
        // issue global loads for chunk c+1
        if (c < NCHUNK - 1) {
            const int seg = (c + 1) >> 5;
            const int k0  = ((c + 1) & 31) * KCH;
            const float* ap = aBase[seg] + k0;
            #pragma unroll
            for (int i = 0; i < 4; i++) av[i] = *reinterpret_cast<const float4*>(ap + (size_t)i * 32 * 1024);
            #pragma unroll
            for (int i = 0; i < 4; i++) bv[i] = *reinterpret_cast<const float4*>(bBase[seg][i] + k0);
        }

        // compute on buffer c&1
        {
            const uint32_t stA = sm_base + (uint32_t)(c & 1) * STAGE_BYTES;
            const uint32_t stB = stA + A_STAGE_BYTES;
            #pragma unroll
            for (int ks = 0; ks < 2; ks++) {
                uint32_t ah[4][4], al[4][4], bh[4][2], bl[4][2];
                #pragma unroll
                for (int mt = 0; mt < 4; mt++) {
                    uint32_t off = arow_b + (uint32_t)(mt * 2048 + ks * 32);
                    ldsm_x4(ah[mt], stA + sw128(off));
                    ldsm_x4(al[mt], stA + sw128(off + 64));
                }
                #pragma unroll
                for (int nt2 = 0; nt2 < 2; nt2++) {
                    uint32_t off = brow_b + (uint32_t)(nt2 * 2048 + ks * 32);
                    uint32_t r[4];
                    ldsm_x4(r, stB + sw128(off));
                    bh[nt2*2][0] = r[0]; bh[nt2*2][1] = r[1];
                    bh[nt2*2+1][0] = r[2]; bh[nt2*2+1][1] = r[3];
                    ldsm_x4(r, stB + sw128(off + 64));
                    bl[nt2*2][0] = r[0]; bl[nt2*2][1] = r[1];
                    bl[nt2*2+1][0] = r[2]; bl[nt2*2+1][1] = r[3];
                }
                #pragma unroll
                for (int mt = 0; mt < 4; mt++)
                    #pragma unroll
                    for (int nt = 0; nt < 4; nt++) {
                        mma_bf16(acc[mt][nt], ah[mt], bh[nt]);
                        mma_bf16(acc[mt][nt], ah[mt], bl[nt]);
                        mma_bf16(acc[mt][nt], al[mt], bh[nt]);
                    }
            }
        }

        // store chunk c+1 into the other buffer
        if (c < NCHUNK - 1) {
            char* sA = dyn + ((c + 1) & 1) * STAGE_BYTES;
            char* sB = sA + A_STAGE_BYTES;
            #pragma unroll
            for (int i = 0; i < 4; i++) {
                uint32_t h01, h23, l01, l23;
                split4(av[i], h01, h23, l01, l23);
                uint32_t off = (uint32_t)((rowgrp + 32 * i) * 128 + colf4 * 8);
                *reinterpret_cast<uint2*>(sA + sw128(off))      = make_uint2(h01, h23);
                *reinterpret_cast<uint2*>(sA + sw128(off + 64)) = make_uint2(l01, l23);
                split4(bv[i], h01, h23, l01, l23);
                *reinterpret_cast<uint2*>(sB + sw128(off))      = make_uint2(h01, h23);
                *reinterpret_cast<uint2*>(sB + sw128(off + 64)) = make_uint2(l01, l23);
            }
        }
        __syncthreads();
    }

    // ---- epilogue: accs -> smem transpose [n][m] ----
    float* Csm = reinterpret_cast<float*>(dyn);   // [128][129]
    {
        const int gid = lane >> 2;
        const int tig = lane & 3;
        #pragma unroll
        for (int mt = 0; mt < 4; mt++)
            #pragma unroll
            for (int nt = 0; nt < 4; nt++) {
                int row = wm * 64 + mt * 16 + gid;
                int col = wn * 32 + nt * 8 + tig * 2;
                Csm[(col    ) * 129 + row    ] = acc[mt][nt][0];
                Csm[(col + 1) * 129 + row    ] = acc[mt][nt][1];
                Csm[(col    ) * 129 + row + 8] = acc[mt][nt][2];
                Csm[(col + 1) * 129 + row + 8] = acc[mt][nt][3];
            }
    }
    __syncthreads();

    // ---- fused LSTM activation + writeout (coalesced over hh) ----
    #pragma unroll
    for (int it = 0; it < 16; it++) {
        int idx = tid + it * 256;           // 4096 = 128 m x 32 hh
        int hh = idx & 31;
        int m  = idx >> 5;
        float gi = Csm[( 0 + hh) * 129 + m] + bias_sm[ 0 + hh];
        float go = Csm[(32 + hh) * 129 + m] + bias_sm[32 + hh];
        float gf = Csm[(64 + hh) * 129 + m] + bias_sm[64 + hh];
        float gc = Csm[(96 + hh) * 129 + m] + bias_sm[96 + hh];
        size_t g = (size_t)(m0 + m) * 1024 + h0 + hh;
        float ig = fast_sig(gi);
        float og = fast_sig(go);
        float fg = fast_sig(gf);
        float ct = fast_tanh(gc);
        float nc = fg * oldc[g] + ig * ct;
        outh[g] = og * fast_tanh(nc);
        outc[g] = nc;
    }
}

extern "C" void kernel_launch(void* const* d_in, const int* in_sizes, int n_in,
                              void* d_out, int out_size)
{
    const float* incoming = (const float*)d_in[0];
    const float* old_h    = (const float*)d_in[1];
    const float* old_c    = (const float*)d_in[2];

    GateParams gp;
    gp.w[0] = (const float*)d_in[3];  gp.b[0] = (const float*)d_in[4];  gp.u[0] = (const float*)d_in[5];
    gp.w[1] = (const float*)d_in[6];  gp.b[1] = (const float*)d_in[7];  gp.u[1] = (const float*)d_in[8];
    gp.w[2] = (const float*)d_in[9];  gp.b[2] = (const float*)d_in[10]; gp.u[2] = (const float*)d_in[11];
    gp.w[3] = (const float*)d_in[12]; gp.b[3] = (const float*)d_in[13]; gp.u[3] = (const float*)d_in[14];

    float* out_h = (float*)d_out;
    float* out_c = out_h + (size_t)BATCHSZ * HID;

    cudaFuncSetAttribute(lstm_hmma_kernel, cudaFuncAttributeMaxDynamicSharedMemorySize, DYN_BYTES);

    dim3 grid(HID / 32, BATCHSZ / 128);   // 32 x 32 = 1024 CTAs
    lstm_hmma_kernel<<<grid, THREADS, DYN_BYTES>>>(incoming, old_h, old_c, gp, out_h, out_c);
}

// round 4
// speedup vs baseline: 2.7230x; 1.1642x over previous
#include <cuda_runtime.h>
#include <cuda_bf16.h>
#include <cstdint>

// LSTMCell fused, two kernels:
//  1) convert_kernel: fp32 -> packed (hi|lo) bf16 split of X,H,W,U into a
//     __device__ scratch laid out exactly as the GEMM smem tiles
//     (per row, per 32-K chunk: 64B hi bf16 | 64B lo bf16 = 128B).
//  2) lstm_hmma_kernel: mma.sync bf16 3-term (Ah*Bh + Ah*Bl + Al*Bh) GEMM,
//     fp32 accumulate, cp.async 5-stage smem pipeline, fused LSTM epilogue.
// B=4096, I=H=1024. CTA tile M=128 x N=128 (32 h x 4 gates). K=2048.

#define HID     1024
#define BATCHSZ 4096
#define KCH     32
#define NCHUNK  64
#define THREADS 256
#define STAGES  5

#define A_STAGE_BYTES (128*128)                 // 16 KB
#define STAGE_BYTES   (2*A_STAGE_BYTES)         // A+B = 32 KB
#define DYN_BYTES     (STAGES*STAGE_BYTES + 1024)

// Scratch: 16384 rows x 4096 B.
// rows [0,4096): X | [4096,8192): H
// rows [8192,16384): 8192 + seg*4096 + gate*1024 + h   (seg 0 = W, 1 = U)
__device__ __align__(128) unsigned char g_scr[(size_t)16384 * 4096];

struct GateParams { const float* w[4]; const float* u[4]; const float* b[4]; };

static __device__ __forceinline__ uint32_t smem_u32(const void* p) {
    uint32_t a;
    asm("{ .reg .u64 t; cvta.to.shared.u64 t, %1; cvt.u32.u64 %0, t; }" : "=r"(a) : "l"(p));
    return a;
}
static __device__ __forceinline__ uint32_t sw128(uint32_t off) {
    return off ^ ((off >> 3) & 0x70);
}
static __device__ __forceinline__ void ldsm_x4(uint32_t* r, uint32_t addr) {
    asm volatile("ldmatrix.sync.aligned.m8n8.x4.shared.b16 {%0,%1,%2,%3}, [%4];"
        : "=r"(r[0]), "=r"(r[1]), "=r"(r[2]), "=r"(r[3]) : "r"(addr));
}
static __device__ __forceinline__ void mma_bf16(float* c, const uint32_t* a, const uint32_t* b) {
    asm volatile("mma.sync.aligned.m16n8k16.row.col.f32.bf16.bf16.f32 "
        "{%0,%1,%2,%3}, {%4,%5,%6,%7}, {%8,%9}, {%0,%1,%2,%3};"
        : "+f"(c[0]), "+f"(c[1]), "+f"(c[2]), "+f"(c[3])
        : "r"(a[0]), "r"(a[1]), "r"(a[2]), "r"(a[3]), "r"(b[0]), "r"(b[1]));
}
#define CP_ASYNC16(dst, src) asm volatile("cp.async.cg.shared.global [%0], [%1], 16;" :: "r"(dst), "l"(src))
#define CP_COMMIT()          asm volatile("cp.async.commit_group;" ::: "memory")
#define CP_WAIT(n)           asm volatile("cp.async.wait_group %0;" :: "n"(n) : "memory")

static __device__ __forceinline__ void split4(float4 v, uint32_t& h01, uint32_t& h23,
                                              uint32_t& l01, uint32_t& l23) {
    __nv_bfloat162 H01 = __floats2bfloat162_rn(v.x, v.y);
    __nv_bfloat162 H23 = __floats2bfloat162_rn(v.z, v.w);
    float2 f01 = __bfloat1622float2(H01);
    float2 f23 = __bfloat1622float2(H23);
    __nv_bfloat162 L01 = __floats2bfloat162_rn(v.x - f01.x, v.y - f01.y);
    __nv_bfloat162 L23 = __floats2bfloat162_rn(v.z - f23.x, v.w - f23.y);
    h01 = *reinterpret_cast<uint32_t*>(&H01);
    h23 = *reinterpret_cast<uint32_t*>(&H23);
    l01 = *reinterpret_cast<uint32_t*>(&L01);
    l23 = *reinterpret_cast<uint32_t*>(&L23);
}

static __device__ __forceinline__ float fast_sig(float x)  { return 1.0f / (1.0f + __expf(-x)); }
static __device__ __forceinline__ float fast_tanh(float x) { float e = __expf(2.0f * x); return 1.0f - 2.0f / (e + 1.0f); }

// ---- pre-pass: one block per scratch row (1024 floats), one float4 per thread
__global__ __launch_bounds__(256)
void convert_kernel(const float* __restrict__ X, const float* __restrict__ Hs, GateParams gp)
{
    const int row = blockIdx.x;
    const int t   = threadIdx.x;           // 0..255 -> float4 index in row

    const float* src;
    if (row < 4096)       src = X  + (size_t)row * 1024;
    else if (row < 8192)  src = Hs + (size_t)(row - 4096) * 1024;
    else {
        int r2  = row - 8192;
        int seg = r2 >> 12;
        int g   = (r2 >> 10) & 3;
        int hh  = r2 & 1023;
        src = (seg ? gp.u[g] : gp.w[g]) + (size_t)hh * 1024;
    }

    float4 v = *reinterpret_cast<const float4*>(src + t * 4);
    uint32_t h01, h23, l01, l23;
    split4(v, h01, h23, l01, l23);

    unsigned char* dst = g_scr + (size_t)row * 4096;
    const int kc  = t >> 3;        // 32-K chunk
    const int blk = t & 7;         // 8B block within half-row
    *reinterpret_cast<uint2*>(dst + kc * 128 + blk * 8)      = make_uint2(h01, h23);
    *reinterpret_cast<uint2*>(dst + kc * 128 + 64 + blk * 8) = make_uint2(l01, l23);
}

__global__ __launch_bounds__(THREADS, 1)
void lstm_hmma_kernel(const float* __restrict__ oldc, GateParams gp,
                      float* __restrict__ outh, float* __restrict__ outc)
{
    extern __shared__ char dyn_raw[];
    char* dyn = (char*)(((uintptr_t)dyn_raw + 1023) & ~(uintptr_t)1023);
    __shared__ float bias_sm[128];

    const int tid  = threadIdx.x;
    const int lane = tid & 31;
    const int warp = tid >> 5;
    const int wm   = warp >> 2;
    const int wn   = warp & 3;
    const int h0   = blockIdx.x * 32;
    const int m0   = blockIdx.y * 128;

    if (tid < 128) bias_sm[tid] = gp.b[tid >> 5][h0 + (tid & 31)];

    const int colf4  = tid & 7;     // 16B block within 128B row
    const int rowgrp = tid >> 3;    // 0..31; handles rows rowgrp+32i

    const uint32_t sm_base = smem_u32(dyn);
    const uint32_t arow_b = (uint32_t)((wm * 64 + (lane & 15)) * 128) + ((lane >> 4) << 4);
    const uint32_t brow_b = (uint32_t)((wn * 32 + ((lane >> 4) << 3) + (lane & 7)) * 128) + (((lane >> 3) & 1) << 4);

    // cp.async smem destination offsets (within a stage buffer), i = 0..3
    uint32_t adst[4], bdst[4];
    #pragma unroll
    for (int i = 0; i < 4; i++) {
        uint32_t off = sw128((uint32_t)((rowgrp + 32 * i) * 128 + colf4 * 16));
        adst[i] = off;
        bdst[i] = (uint32_t)A_STAGE_BYTES + off;
    }

    // issue all cp.async for chunk c into stage buffer `buf`
    auto issue_chunk = [&](int c, uint32_t bufsm) {
        const int seg = c >> 5;
        const int kc  = c & 31;
        const unsigned char* abase = g_scr + ((size_t)(seg * 4096 + m0 + rowgrp)) * 4096 + kc * 128 + colf4 * 16;
        const unsigned char* bbase = g_scr + ((size_t)(8192 + seg * 4096 + h0 + rowgrp)) * 4096 + kc * 128 + colf4 * 16;
        #pragma unroll
        for (int i = 0; i < 4; i++) {
            CP_ASYNC16(bufsm + adst[i], abase + (size_t)i * 32 * 4096);   // rows m0+rowgrp+32i
            CP_ASYNC16(bufsm + bdst[i], bbase + (size_t)i * 1024 * 4096); // gate i, row h0+rowgrp
        }
    };

    float acc[4][4][4];
    #pragma unroll
    for (int mt = 0; mt < 4; mt++)
        #pragma unroll
        for (int nt = 0; nt < 4; nt++)
            #pragma unroll
            for (int q = 0; q < 4; q++) acc[mt][nt][q] = 0.0f;

    // prologue: stages 0..STAGES-2
    #pragma unroll
    for (int p = 0; p < STAGES - 1; p++) {
        issue_chunk(p, sm_base + p * STAGE_BYTES);
        CP_COMMIT();
    }
    CP_WAIT(STAGES - 2);
    __syncthreads();

    int buf = 0;
    for (int c = 0; c < NCHUNK; c++) {
        // issue chunk c+STAGES-1 into the buffer freed at iter c-1
        int nc2 = c + STAGES - 1;
        if (nc2 < NCHUNK) {
            int nb = buf + STAGES - 1; if (nb >= STAGES) nb -= STAGES;
            issue_chunk(nc2, sm_base + nb * STAGE_BYTES);
        }
        CP_COMMIT();

        // compute chunk c from buffer `buf`
        {
            const uint32_t stA = sm_base + buf * STAGE_BYTES;
            const uint32_t stB = stA + A_STAGE_BYTES;
            #pragma unroll
            for (int ks = 0; ks < 2; ks++) {
                uint32_t ah[4][4], al[4][4], bh[4][2], bl[4][2];
                #pragma unroll
                for (int mt = 0; mt < 4; mt++) {
                    uint32_t off = arow_b + (uint32_t)(mt * 2048 + ks * 32);
                    ldsm_x4(ah[mt], stA + sw128(off));
                    ldsm_x4(al[mt], stA + sw128(off + 64));
                }
                #pragma unroll
                for (int nt2 = 0; nt2 < 2; nt2++) {
                    uint32_t off = brow_b + (uint32_t)(nt2 * 2048 + ks * 32);
                    uint32_t r[4];
                    ldsm_x4(r, stB + sw128(off));
                    bh[nt2*2][0] = r[0]; bh[nt2*2][1] = r[1];
                    bh[nt2*2+1][0] = r[2]; bh[nt2*2+1][1] = r[3];
                    ldsm_x4(r, stB + sw128(off + 64));
                    bl[nt2*2][0] = r[0]; bl[nt2*2][1] = r[1];
                    bl[nt2*2+1][0] = r[2]; bl[nt2*2+1][1] = r[3];
                }
                #pragma unroll
                for (int mt = 0; mt < 4; mt++)
                    #pragma unroll
                    for (int nt = 0; nt < 4; nt++) {
                        mma_bf16(acc[mt][nt], ah[mt], bh[nt]);
                        mma_bf16(acc[mt][nt], ah[mt], bl[nt]);
                        mma_bf16(acc[mt][nt], al[mt], bh[nt]);
                    }
            }
        }

        CP_WAIT(STAGES - 2);
        __syncthreads();
        if (++buf == STAGES) buf = 0;
    }

    // ---- epilogue: accs -> smem transpose [n][m], then fused LSTM ----
    float* Csm = reinterpret_cast<float*>(dyn);   // [128][129] floats (66 KB < arena)
    {
        const int gid = lane >> 2;
        const int tig = lane & 3;
        #pragma unroll
        for (int mt = 0; mt < 4; mt++)
            #pragma unroll
            for (int nt = 0; nt < 4; nt++) {
                int row = wm * 64 + mt * 16 + gid;
                int col = wn * 32 + nt * 8 + tig * 2;
                Csm[(col    ) * 129 + row    ] = acc[mt][nt][0];
                Csm[(col + 1) * 129 + row    ] = acc[mt][nt][1];
                Csm[(col    ) * 129 + row + 8] = acc[mt][nt][2];
                Csm[(col + 1) * 129 + row + 8] = acc[mt][nt][3];
            }
    }
    __syncthreads();

    #pragma unroll
    for (int it = 0; it < 16; it++) {
        int idx = tid + it * 256;
        int hh = idx & 31;
        int m  = idx >> 5;
        float gi = Csm[( 0 + hh) * 129 + m] + bias_sm[ 0 + hh];
        float go = Csm[(32 + hh) * 129 + m] + bias_sm[32 + hh];
        float gf = Csm[(64 + hh) * 129 + m] + bias_sm[64 + hh];
        float gc = Csm[(96 + hh) * 129 + m] + bias_sm[96 + hh];
        size_t g = (size_t)(m0 + m) * 1024 + h0 + hh;
        float ig = fast_sig(gi);
        float og = fast_sig(go);
        float fg = fast_sig(gf);
        float ct = fast_tanh(gc);
        float nc = fg * oldc[g] + ig * ct;
        outh[g] = og * fast_tanh(nc);
        outc[g] = nc;
    }
}

extern "C" void kernel_launch(void* const* d_in, const int* in_sizes, int n_in,
                              void* d_out, int out_size)
{
    const float* incoming = (const float*)d_in[0];
    const float* old_h    = (const float*)d_in[1];
    const float* old_c    = (const float*)d_in[2];

    GateParams gp;
    gp.w[0] = (const float*)d_in[3];  gp.b[0] = (const float*)d_in[4];  gp.u[0] = (const float*)d_in[5];
    gp.w[1] = (const float*)d_in[6];  gp.b[1] = (const float*)d_in[7];  gp.u[1] = (const float*)d_in[8];
    gp.w[2] = (const float*)d_in[9];  gp.b[2] = (const float*)d_in[10]; gp.u[2] = (const float*)d_in[11];
    gp.w[3] = (const float*)d_in[12]; gp.b[3] = (const float*)d_in[13]; gp.u[3] = (const float*)d_in[14];

    float* out_h = (float*)d_out;
    float* out_c = out_h + (size_t)BATCHSZ * HID;

    convert_kernel<<<16384, 256>>>(incoming, old_h, gp);

    cudaFuncSetAttribute(lstm_hmma_kernel, cudaFuncAttributeMaxDynamicSharedMemorySize, DYN_BYTES);
    dim3 grid(HID / 32, BATCHSZ / 128);   // 32 x 32 = 1024 CTAs
    lstm_hmma_kernel<<<grid, THREADS, DYN_BYTES>>>(old_c, gp, out_h, out_c);
}

// round 5
// speedup vs baseline: 2.7676x; 1.0164x over previous
#include <cuda_runtime.h>
#include <cuda_bf16.h>
#include <cstdint>

// LSTMCell fused, two kernels:
//  1) convert_kernel: fp32 -> packed (hi|lo) bf16 split of X,H,W,U into a
//     __device__ scratch laid out exactly as the GEMM smem tiles
//     (per row, per 32-K chunk: 64B hi bf16 | 64B lo bf16 = 128B).
//  2) lstm_hmma_kernel: mma.sync bf16 3-term (Ah*Bh + Ah*Bl + Al*Bh) GEMM,
//     fp32 accumulate, cp.async 3-stage x 64-K-chunk smem ring, fused epilogue.
// B=4096, I=H=1024. CTA tile M=128 x N=128 (32 h x 4 gates). K=2048.

#define HID     1024
#define BATCHSZ 4096
#define NCHUNK  32          // 2048 / 64
#define THREADS 256
#define STAGES  3

#define CHUNK_TILE (128*128)                    // 16 KB: one 32-K sub-chunk tile
#define STAGE_BYTES (4*CHUNK_TILE)              // A0 A1 B0 B1 = 64 KB
#define DYN_BYTES   (STAGES*STAGE_BYTES + 1024) // 193 KB

// Scratch: 16384 rows x 4096 B.
// rows [0,4096): X | [4096,8192): H
// rows [8192,16384): 8192 + seg*4096 + gate*1024 + h   (seg 0 = W, 1 = U)
__device__ __align__(128) unsigned char g_scr[(size_t)16384 * 4096];

struct GateParams { const float* w[4]; const float* u[4]; const float* b[4]; };

static __device__ __forceinline__ uint32_t smem_u32(const void* p) {
    uint32_t a;
    asm("{ .reg .u64 t; cvta.to.shared.u64 t, %1; cvt.u32.u64 %0, t; }" : "=r"(a) : "l"(p));
    return a;
}
static __device__ __forceinline__ uint32_t sw128(uint32_t off) {
    return off ^ ((off >> 3) & 0x70);
}
static __device__ __forceinline__ void ldsm_x4(uint32_t* r, uint32_t addr) {
    asm volatile("ldmatrix.sync.aligned.m8n8.x4.shared.b16 {%0,%1,%2,%3}, [%4];"
        : "=r"(r[0]), "=r"(r[1]), "=r"(r[2]), "=r"(r[3]) : "r"(addr));
}
static __device__ __forceinline__ void mma_bf16(float* c, const uint32_t* a, const uint32_t* b) {
    asm volatile("mma.sync.aligned.m16n8k16.row.col.f32.bf16.bf16.f32 "
        "{%0,%1,%2,%3}, {%4,%5,%6,%7}, {%8,%9}, {%0,%1,%2,%3};"
        : "+f"(c[0]), "+f"(c[1]), "+f"(c[2]), "+f"(c[3])
        : "r"(a[0]), "r"(a[1]), "r"(a[2]), "r"(a[3]), "r"(b[0]), "r"(b[1]));
}
#define CP_ASYNC16(dst, src) asm volatile("cp.async.cg.shared.global [%0], [%1], 16;" :: "r"(dst), "l"(src))
#define CP_COMMIT()          asm volatile("cp.async.commit_group;" ::: "memory")
#define CP_WAIT(n)           asm volatile("cp.async.wait_group %0;" :: "n"(n) : "memory")

static __device__ __forceinline__ void split4(float4 v, uint32_t& h01, uint32_t& h23,
                                              uint32_t& l01, uint32_t& l23) {
    __nv_bfloat162 H01 = __floats2bfloat162_rn(v.x, v.y);
    __nv_bfloat162 H23 = __floats2bfloat162_rn(v.z, v.w);
    float2 f01 = __bfloat1622float2(H01);
    float2 f23 = __bfloat1622float2(H23);
    __nv_bfloat162 L01 = __floats2bfloat162_rn(v.x - f01.x, v.y - f01.y);
    __nv_bfloat162 L23 = __floats2bfloat162_rn(v.z - f23.x, v.w - f23.y);
    h01 = *reinterpret_cast<uint32_t*>(&H01);
    h23 = *reinterpret_cast<uint32_t*>(&H23);
    l01 = *reinterpret_cast<uint32_t*>(&L01);
    l23 = *reinterpret_cast<uint32_t*>(&L23);
}

static __device__ __forceinline__ float fast_sig(float x)  { return 1.0f / (1.0f + __expf(-x)); }
static __device__ __forceinline__ float fast_tanh(float x) { float e = __expf(2.0f * x); return 1.0f - 2.0f / (e + 1.0f); }

// ---- pre-pass: one block per scratch row (1024 floats), one float4 per thread
__global__ __launch_bounds__(256)
void convert_kernel(const float* __restrict__ X, const float* __restrict__ Hs, GateParams gp)
{
    const int row = blockIdx.x;
    const int t   = threadIdx.x;

    const float* src;
    if (row < 4096)       src = X  + (size_t)row * 1024;
    else if (row < 8192)  src = Hs + (size_t)(row - 4096) * 1024;
    else {
        int r2  = row - 8192;
        int seg = r2 >> 12;
        int g   = (r2 >> 10) & 3;
        int hh  = r2 & 1023;
        src = (seg ? gp.u[g] : gp.w[g]) + (size_t)hh * 1024;
    }

    float4 v = *reinterpret_cast<const float4*>(src + t * 4);
    uint32_t h01, h23, l01, l23;
    split4(v, h01, h23, l01, l23);

    unsigned char* dst = g_scr + (size_t)row * 4096;
    const int kc  = t >> 3;
    const int blk = t & 7;
    *reinterpret_cast<uint2*>(dst + kc * 128 + blk * 8)      = make_uint2(h01, h23);
    *reinterpret_cast<uint2*>(dst + kc * 128 + 64 + blk * 8) = make_uint2(l01, l23);
}

__global__ __launch_bounds__(THREADS, 1)
void lstm_hmma_kernel(const float* __restrict__ oldc, GateParams gp,
                      float* __restrict__ outh, float* __restrict__ outc)
{
    extern __shared__ char dyn_raw[];
    char* dyn = (char*)(((uintptr_t)dyn_raw + 1023) & ~(uintptr_t)1023);
    __shared__ float bias_sm[128];

    const int tid  = threadIdx.x;
    const int lane = tid & 31;
    const int warp = tid >> 5;
    const int wm   = warp >> 2;
    const int wn   = warp & 3;
    const int h0   = blockIdx.x * 32;
    const int m0   = blockIdx.y * 128;

    if (tid < 128) bias_sm[tid] = gp.b[tid >> 5][h0 + (tid & 31)];

    const int colf4  = tid & 7;     // 16B block within 128B row
    const int rowgrp = tid >> 3;    // 0..31; handles rows rowgrp+32i

    const uint32_t sm_base = smem_u32(dyn);
    const uint32_t arow_b = (uint32_t)((wm * 64 + (lane & 15)) * 128) + ((lane >> 4) << 4);
    const uint32_t brow_b = (uint32_t)((wn * 32 + ((lane >> 4) << 3) + (lane & 7)) * 128) + (((lane >> 3) & 1) << 4);

    // cp.async smem dest offsets within a 16 KB chunk tile, i = 0..3 (rows +32i)
    uint32_t tdst[4];
    #pragma unroll
    for (int i = 0; i < 4; i++)
        tdst[i] = sw128((uint32_t)((rowgrp + 32 * i) * 128 + colf4 * 16));

    // issue all cp.async for 64-K chunk c (two 32-K sub-chunks) into stage buffer
    auto issue_chunk = [&](int c, uint32_t bufsm) {
        const int seg = c >> 4;
        const int kc2 = (c & 15) * 2;   // first 32-K sub-chunk index
        const unsigned char* abase = g_scr + ((size_t)(seg * 4096 + m0 + rowgrp)) * 4096 + kc2 * 128 + colf4 * 16;
        const unsigned char* bbase = g_scr + ((size_t)(8192 + seg * 4096 + h0 + rowgrp)) * 4096 + kc2 * 128 + colf4 * 16;
        #pragma unroll
        for (int s = 0; s < 2; s++) {        // sub-chunk (A0/A1, B0/B1)
            #pragma unroll
            for (int i = 0; i < 4; i++) {
                CP_ASYNC16(bufsm + s * CHUNK_TILE + tdst[i],
                           abase + (size_t)i * 32 * 4096 + s * 128);
                CP_ASYNC16(bufsm + (2 + s) * CHUNK_TILE + tdst[i],
                           bbase + (size_t)i * 1024 * 4096 + s * 128);
            }
        }
    };

    float acc[4][4][4];
    #pragma unroll
    for (int mt = 0; mt < 4; mt++)
        #pragma unroll
        for (int nt = 0; nt < 4; nt++)
            #pragma unroll
            for (int q = 0; q < 4; q++) acc[mt][nt][q] = 0.0f;

    // prologue: stages 0..STAGES-2
    #pragma unroll
    for (int p = 0; p < STAGES - 1; p++) {
        issue_chunk(p, sm_base + p * STAGE_BYTES);
        CP_COMMIT();
    }
    CP_WAIT(STAGES - 2);
    __syncthreads();

    int buf = 0;
    for (int c = 0; c < NCHUNK; c++) {
        int nc2 = c + STAGES - 1;
        if (nc2 < NCHUNK) {
            int nb = buf + STAGES - 1; if (nb >= STAGES) nb -= STAGES;
            issue_chunk(nc2, sm_base + nb * STAGE_BYTES);
        }
        CP_COMMIT();

        // compute 64-K chunk c from stage `buf`: 4 k16 steps
        {
            const uint32_t st = sm_base + buf * STAGE_BYTES;
            #pragma unroll
            for (int ks = 0; ks < 4; ks++) {
                const uint32_t stA = st + (ks >> 1) * CHUNK_TILE;
                const uint32_t stB = st + (2 + (ks >> 1)) * CHUNK_TILE;
                const uint32_t ko  = (uint32_t)(ks & 1) * 32;
                uint32_t ah[4][4], al[4][4], bh[4][2], bl[4][2];
                #pragma unroll
                for (int mt = 0; mt < 4; mt++) {
                    uint32_t off = arow_b + (uint32_t)(mt * 2048) + ko;
                    ldsm_x4(ah[mt], stA + sw128(off));
                    ldsm_x4(al[mt], stA + sw128(off + 64));
                }
                #pragma unroll
                for (int nt2 = 0; nt2 < 2; nt2++) {
                    uint32_t off = brow_b + (uint32_t)(nt2 * 2048) + ko;
                    uint32_t r[4];
                    ldsm_x4(r, stB + sw128(off));
                    bh[nt2*2][0] = r[0]; bh[nt2*2][1] = r[1];
                    bh[nt2*2+1][0] = r[2]; bh[nt2*2+1][1] = r[3];
                    ldsm_x4(r, stB + sw128(off + 64));
                    bl[nt2*2][0] = r[0]; bl[nt2*2][1] = r[1];
                    bl[nt2*2+1][0] = r[2]; bl[nt2*2+1][1] = r[3];
                }
                #pragma unroll
                for (int mt = 0; mt < 4; mt++)
                    #pragma unroll
                    for (int nt = 0; nt < 4; nt++) {
                        mma_bf16(acc[mt][nt], ah[mt], bh[nt]);
                        mma_bf16(acc[mt][nt], ah[mt], bl[nt]);
                        mma_bf16(acc[mt][nt], al[mt], bh[nt]);
                    }
            }
        }

        CP_WAIT(STAGES - 2);
        __syncthreads();
        if (++buf == STAGES) buf = 0;
    }

    // ---- epilogue: accs -> smem transpose [n][m], then fused LSTM ----
    float* Csm = reinterpret_cast<float*>(dyn);   // [128][129] floats (66 KB)
    {
        const int gid = lane >> 2;
        const int tig = lane & 3;
        #pragma unroll
        for (int mt = 0; mt < 4; mt++)
            #pragma unroll
            for (int nt = 0; nt < 4; nt++) {
                int row = wm * 64 + mt * 16 + gid;
                int col = wn * 32 + nt * 8 + tig * 2;
                Csm[(col    ) * 129 + row    ] = acc[mt][nt][0];
                Csm[(col + 1) * 129 + row    ] = acc[mt][nt][1];
                Csm[(col    ) * 129 + row + 8] = acc[mt][nt][2];
                Csm[(col + 1) * 129 + row + 8] = acc[mt][nt][3];
            }
    }
    __syncthreads();

    #pragma unroll
    for (int it = 0; it < 16; it++) {
        int idx = tid + it * 256;
        int hh = idx & 31;
        int m  = idx >> 5;
        float gi = Csm[( 0 + hh) * 129 + m] + bias_sm[ 0 + hh];
        float go = Csm[(32 + hh) * 129 + m] + bias_sm[32 + hh];
        float gf = Csm[(64 + hh) * 129 + m] + bias_sm[64 + hh];
        float gc = Csm[(96 + hh) * 129 + m] + bias_sm[96 + hh];
        size_t g = (size_t)(m0 + m) * 1024 + h0 + hh;
        float ig = fast_sig(gi);
        float og = fast_sig(go);
        float fg = fast_sig(gf);
        float ct = fast_tanh(gc);
        float nc = fg * oldc[g] + ig * ct;
        outh[g] = og * fast_tanh(nc);
        outc[g] = nc;
    }
}

extern "C" void kernel_launch(void* const* d_in, const int* in_sizes, int n_in,
                              void* d_out, int out_size)
{
    const float* incoming = (const float*)d_in[0];
    const float* old_h    = (const float*)d_in[1];
    const float* old_c    = (const float*)d_in[2];

    GateParams gp;
    gp.w[0] = (const float*)d_in[3];  gp.b[0] = (const float*)d_in[4];  gp.u[0] = (const float*)d_in[5];
    gp.w[1] = (const float*)d_in[6];  gp.b[1] = (const float*)d_in[7];  gp.u[1] = (const float*)d_in[8];
    gp.w[2] = (const float*)d_in[9];  gp.b[2] = (const float*)d_in[10]; gp.u[2] = (const float*)d_in[11];
    gp.w[3] = (const float*)d_in[12]; gp.b[3] = (const float*)d_in[13]; gp.u[3] = (const float*)d_in[14];

    float* out_h = (float*)d_out;
    float* out_c = out_h + (size_t)BATCHSZ * HID;

    convert_kernel<<<16384, 256>>>(incoming, old_h, gp);

    cudaFuncSetAttribute(lstm_hmma_kernel, cudaFuncAttributeMaxDynamicSharedMemorySize, DYN_BYTES);
    dim3 grid(HID / 32, BATCHSZ / 128);   // 32 x 32 = 1024 CTAs
    lstm_hmma_kernel<<<grid, THREADS, DYN_BYTES>>>(old_c, gp, out_h, out_c);
}

// round 6
// speedup vs baseline: 3.1070x; 1.1226x over previous
#include <cuda_runtime.h>
#include <cuda_bf16.h>
#include <cstdint>

// LSTMCell fused, two kernels:
//  1) convert_kernel: fp32 -> packed (hi|lo) bf16 split of X,H,W,U into a
//     __device__ scratch laid out exactly as the GEMM smem tiles.
//  2) lstm_hmma_kernel: mma.sync bf16 3-term (Ah*Bh + Ah*Bl + Al*Bh) GEMM,
//     fp32 accumulate, cp.async 3-stage ring, 2 CTAs/SM, fused LSTM epilogue.
// B=4096, I=H=1024. CTA tile M=128 x N=128 (32 h x 4 gates). K=2048.

#define HID     1024
#define BATCHSZ 4096
#define NCHUNK  64          // 2048 / 32
#define THREADS 256
#define STAGES  3

#define A_STAGE_BYTES (128*128)                 // 16 KB
#define STAGE_BYTES   (2*A_STAGE_BYTES)         // 32 KB
#define DYN_BYTES     (STAGES*STAGE_BYTES + 1024)   // 97 KB -> 2 CTAs/SM

// Scratch: 16384 rows x 4096 B.
// rows [0,4096): X | [4096,8192): H
// rows [8192,16384): 8192 + seg*4096 + gate*1024 + h   (seg 0 = W, 1 = U)
__device__ __align__(128) unsigned char g_scr[(size_t)16384 * 4096];

struct GateParams { const float* w[4]; const float* u[4]; const float* b[4]; };

static __device__ __forceinline__ uint32_t smem_u32(const void* p) {
    uint32_t a;
    asm("{ .reg .u64 t; cvta.to.shared.u64 t, %1; cvt.u32.u64 %0, t; }" : "=r"(a) : "l"(p));
    return a;
}
static __device__ __forceinline__ uint32_t sw128(uint32_t off) {
    return off ^ ((off >> 3) & 0x70);
}
static __device__ __forceinline__ void ldsm_x4(uint32_t* r, uint32_t addr) {
    asm volatile("ldmatrix.sync.aligned.m8n8.x4.shared.b16 {%0,%1,%2,%3}, [%4];"
        : "=r"(r[0]), "=r"(r[1]), "=r"(r[2]), "=r"(r[3]) : "r"(addr));
}
static __device__ __forceinline__ void mma_bf16(float* c, const uint32_t* a, const uint32_t* b) {
    asm volatile("mma.sync.aligned.m16n8k16.row.col.f32.bf16.bf16.f32 "
        "{%0,%1,%2,%3}, {%4,%5,%6,%7}, {%8,%9}, {%0,%1,%2,%3};"
        : "+f"(c[0]), "+f"(c[1]), "+f"(c[2]), "+f"(c[3])
        : "r"(a[0]), "r"(a[1]), "r"(a[2]), "r"(a[3]), "r"(b[0]), "r"(b[1]));
}
#define CP_ASYNC16(dst, src) asm volatile("cp.async.cg.shared.global [%0], [%1], 16;" :: "r"(dst), "l"(src))
#define CP_COMMIT()          asm volatile("cp.async.commit_group;" ::: "memory")
#define CP_WAIT(n)           asm volatile("cp.async.wait_group %0;" :: "n"(n) : "memory")

static __device__ __forceinline__ void split4(float4 v, uint32_t& h01, uint32_t& h23,
                                              uint32_t& l01, uint32_t& l23) {
    __nv_bfloat162 H01 = __floats2bfloat162_rn(v.x, v.y);
    __nv_bfloat162 H23 = __floats2bfloat162_rn(v.z, v.w);
    float2 f01 = __bfloat1622float2(H01);
    float2 f23 = __bfloat1622float2(H23);
    __nv_bfloat162 L01 = __floats2bfloat162_rn(v.x - f01.x, v.y - f01.y);
    __nv_bfloat162 L23 = __floats2bfloat162_rn(v.z - f23.x, v.w - f23.y);
    h01 = *reinterpret_cast<uint32_t*>(&H01);
    h23 = *reinterpret_cast<uint32_t*>(&H23);
    l01 = *reinterpret_cast<uint32_t*>(&L01);
    l23 = *reinterpret_cast<uint32_t*>(&L23);
}

static __device__ __forceinline__ float fast_sig(float x)  { return 1.0f / (1.0f + __expf(-x)); }
static __device__ __forceinline__ float fast_tanh(float x) { float e = __expf(2.0f * x); return 1.0f - 2.0f / (e + 1.0f); }

__global__ __launch_bounds__(256)
void convert_kernel(const float* __restrict__ X, const float* __restrict__ Hs, GateParams gp)
{
    const int row = blockIdx.x;
    const int t   = threadIdx.x;

    const float* src;
    if (row < 4096)       src = X  + (size_t)row * 1024;
    else if (row < 8192)  src = Hs + (size_t)(row - 4096) * 1024;
    else {
        int r2  = row - 8192;
        int seg = r2 >> 12;
        int g   = (r2 >> 10) & 3;
        int hh  = r2 & 1023;
        src = (seg ? gp.u[g] : gp.w[g]) + (size_t)hh * 1024;
    }

    float4 v = *reinterpret_cast<const float4*>(src + t * 4);
    uint32_t h01, h23, l01, l23;
    split4(v, h01, h23, l01, l23);

    unsigned char* dst = g_scr + (size_t)row * 4096;
    const int kc  = t >> 3;
    const int blk = t & 7;
    *reinterpret_cast<uint2*>(dst + kc * 128 + blk * 8)      = make_uint2(h01, h23);
    *reinterpret_cast<uint2*>(dst + kc * 128 + 64 + blk * 8) = make_uint2(l01, l23);
}

__global__ __launch_bounds__(THREADS, 2)
void lstm_hmma_kernel(const float* __restrict__ oldc, GateParams gp,
                      float* __restrict__ outh, float* __restrict__ outc)
{
    extern __shared__ char dyn_raw[];
    char* dyn = (char*)(((uintptr_t)dyn_raw + 1023) & ~(uintptr_t)1023);
    __shared__ float bias_sm[128];

    const int tid  = threadIdx.x;
    const int lane = tid & 31;
    const int warp = tid >> 5;
    const int wm   = warp >> 2;
    const int wn   = warp & 3;
    const int h0   = blockIdx.x * 32;
    const int m0   = blockIdx.y * 128;

    if (tid < 128) bias_sm[tid] = gp.b[tid >> 5][h0 + (tid & 31)];

    const int colf4  = tid & 7;     // 16B block within 128B row
    const int rowgrp = tid >> 3;    // 0..31; handles rows rowgrp+32i

    const uint32_t sm_base = smem_u32(dyn);
    const uint32_t arow_b = (uint32_t)((wm * 64 + (lane & 15)) * 128) + ((lane >> 4) << 4);
    const uint32_t brow_b = (uint32_t)((wn * 32 + ((lane >> 4) << 3) + (lane & 7)) * 128) + (((lane >> 3) & 1) << 4);

    uint32_t tdst[4];
    #pragma unroll
    for (int i = 0; i < 4; i++)
        tdst[i] = sw128((uint32_t)((rowgrp + 32 * i) * 128 + colf4 * 16));

    auto issue_chunk = [&](int c, uint32_t bufsm) {
        const int seg = c >> 5;
        const int kc  = c & 31;
        const unsigned char* abase = g_scr + ((size_t)(seg * 4096 + m0 + rowgrp)) * 4096 + kc * 128 + colf4 * 16;
        const unsigned char* bbase = g_scr + ((size_t)(8192 + seg * 4096 + h0 + rowgrp)) * 4096 + kc * 128 + colf4 * 16;
        #pragma unroll
        for (int i = 0; i < 4; i++) {
            CP_ASYNC16(bufsm + tdst[i], abase + (size_t)i * 32 * 4096);
            CP_ASYNC16(bufsm + A_STAGE_BYTES + tdst[i], bbase + (size_t)i * 1024 * 4096);
        }
    };

    float acc[4][4][4];
    #pragma unroll
    for (int mt = 0; mt < 4; mt++)
        #pragma unroll
        for (int nt = 0; nt < 4; nt++)
            #pragma unroll
            for (int q = 0; q < 4; q++) acc[mt][nt][q] = 0.0f;

    #pragma unroll
    for (int p = 0; p < STAGES - 1; p++) {
        issue_chunk(p, sm_base + p * STAGE_BYTES);
        CP_COMMIT();
    }
    CP_WAIT(STAGES - 2);
    __syncthreads();

    int buf = 0;
    for (int c = 0; c < NCHUNK; c++) {
        int nc2 = c + STAGES - 1;
        if (nc2 < NCHUNK) {
            int nb = buf + STAGES - 1; if (nb >= STAGES) nb -= STAGES;
            issue_chunk(nc2, sm_base + nb * STAGE_BYTES);
        }
        CP_COMMIT();

        {
            const uint32_t stA = sm_base + buf * STAGE_BYTES;
            const uint32_t stB = stA + A_STAGE_BYTES;
            #pragma unroll
            for (int ks = 0; ks < 2; ks++) {
                uint32_t ah[4][4], al[4][4], bh[4][2], bl[4][2];
                #pragma unroll
                for (int mt = 0; mt < 4; mt++) {
                    uint32_t off = arow_b + (uint32_t)(mt * 2048 + ks * 32);
                    ldsm_x4(ah[mt], stA + sw128(off));
                    ldsm_x4(al[mt], stA + sw128(off + 64));
                }
                #pragma unroll
                for (int nt2 = 0; nt2 < 2; nt2++) {
                    uint32_t off = brow_b + (uint32_t)(nt2 * 2048 + ks * 32);
                    uint32_t r[4];
                    ldsm_x4(r, stB + sw128(off));
                    bh[nt2*2][0] = r[0]; bh[nt2*2][1] = r[1];
                    bh[nt2*2+1][0] = r[2]; bh[nt2*2+1][1] = r[3];
                    ldsm_x4(r, stB + sw128(off + 64));
                    bl[nt2*2][0] = r[0]; bl[nt2*2][1] = r[1];
                    bl[nt2*2+1][0] = r[2]; bl[nt2*2+1][1] = r[3];
                }
                #pragma unroll
                for (int mt = 0; mt < 4; mt++)
                    #pragma unroll
                    for (int nt = 0; nt < 4; nt++) {
                        mma_bf16(acc[mt][nt], ah[mt], bh[nt]);
                        mma_bf16(acc[mt][nt], ah[mt], bl[nt]);
                        mma_bf16(acc[mt][nt], al[mt], bh[nt]);
                    }
            }
        }

        CP_WAIT(STAGES - 2);
        __syncthreads();
        if (++buf == STAGES) buf = 0;
    }

    // ---- epilogue: accs -> smem transpose [n][m], then fused LSTM ----
    float* Csm = reinterpret_cast<float*>(dyn);   // [128][129] floats (66 KB < 97 KB)
    {
        const int gid = lane >> 2;
        const int tig = lane & 3;
        #pragma unroll
        for (int mt = 0; mt < 4; mt++)
            #pragma unroll
            for (int nt = 0; nt < 4; nt++) {
                int row = wm * 64 + mt * 16 + gid;
                int col = wn * 32 + nt * 8 + tig * 2;
                Csm[(col    ) * 129 + row    ] = acc[mt][nt][0];
                Csm[(col + 1) * 129 + row    ] = acc[mt][nt][1];
                Csm[(col    ) * 129 + row + 8] = acc[mt][nt][2];
                Csm[(col + 1) * 129 + row + 8] = acc[mt][nt][3];
            }
    }
    __syncthreads();

    #pragma unroll
    for (int it = 0; it < 16; it++) {
        int idx = tid + it * 256;
        int hh = idx & 31;
        int m  = idx >> 5;
        float gi = Csm[( 0 + hh) * 129 + m] + bias_sm[ 0 + hh];
        float go = Csm[(32 + hh) * 129 + m] + bias_sm[32 + hh];
        float gf = Csm[(64 + hh) * 129 + m] + bias_sm[64 + hh];
        float gc = Csm[(96 + hh) * 129 + m] + bias_sm[96 + hh];
        size_t g = (size_t)(m0 + m) * 1024 + h0 + hh;
        float ig = fast_sig(gi);
        float og = fast_sig(go);
        float fg = fast_sig(gf);
        float ct = fast_tanh(gc);
        float nc = fg * oldc[g] + ig * ct;
        outh[g] = og * fast_tanh(nc);
        outc[g] = nc;
    }
}

extern "C" void kernel_launch(void* const* d_in, const int* in_sizes, int n_in,
                              void* d_out, int out_size)
{
    const float* incoming = (const float*)d_in[0];
    const float* old_h    = (const float*)d_in[1];
    const float* old_c    = (const float*)d_in[2];

    GateParams gp;
    gp.w[0] = (const float*)d_in[3];  gp.b[0] = (const float*)d_in[4];  gp.u[0] = (const float*)d_in[5];
    gp.w[1] = (const float*)d_in[6];  gp.b[1] = (const float*)d_in[7];  gp.u[1] = (const float*)d_in[8];
    gp.w[2] = (const float*)d_in[9];  gp.b[2] = (const float*)d_in[10]; gp.u[2] = (const float*)d_in[11];
    gp.w[3] = (const float*)d_in[12]; gp.b[3] = (const float*)d_in[13]; gp.u[3] = (const float*)d_in[14];

    float* out_h = (float*)d_out;
    float* out_c = out_h + (size_t)BATCHSZ * HID;

    convert_kernel<<<16384, 256>>>(incoming, old_h, gp);

    cudaFuncSetAttribute(lstm_hmma_kernel, cudaFuncAttributeMaxDynamicSharedMemorySize, DYN_BYTES);
    dim3 grid(HID / 32, BATCHSZ / 128);   // 32 x 32 = 1024 CTAs
    lstm_hmma_kernel<<<grid, THREADS, DYN_BYTES>>>(old_c, gp, out_h, out_c);
}

// round 7
// speedup vs baseline: 3.1813x; 1.0239x over previous
#include <cuda_runtime.h>
#include <cuda_bf16.h>
#include <cstdint>

// LSTMCell fused, two kernels:
//  1) convert_kernel: fp32 -> packed (hi|lo) bf16 split of X,H,W,U into a
//     __device__ scratch laid out exactly as the GEMM smem tiles.
//  2) lstm_hmma_kernel: mma.sync bf16 3-term (Ah*Bh + Ah*Bl + Al*Bh) GEMM,
//     fp32 accumulate, cp.async 4-stage ring, 2 CTAs/SM, fused LSTM epilogue.
// B=4096, I=H=1024. CTA tile M=128 x N=64 (16 h x 4 gates) -> grid 2048
// (6.92 waves of 296 -> 98.9% quantization efficiency).

#define HID     1024
#define BATCHSZ 4096
#define NCHUNK  64          // 2048 / 32
#define THREADS 256
#define STAGES  4

#define A_STAGE_BYTES (128*128)                 // 16 KB
#define B_STAGE_BYTES (64*128)                  // 8 KB
#define STAGE_BYTES   (A_STAGE_BYTES + B_STAGE_BYTES)   // 24 KB
#define DYN_BYTES     (STAGES*STAGE_BYTES + 1024)       // 97 KB -> 2 CTAs/SM

// Scratch: 16384 rows x 4096 B.
// rows [0,4096): X | [4096,8192): H
// rows [8192,16384): 8192 + seg*4096 + gate*1024 + h   (seg 0 = W, 1 = U)
__device__ __align__(128) unsigned char g_scr[(size_t)16384 * 4096];

struct GateParams { const float* w[4]; const float* u[4]; const float* b[4]; };

static __device__ __forceinline__ uint32_t smem_u32(const void* p) {
    uint32_t a;
    asm("{ .reg .u64 t; cvta.to.shared.u64 t, %1; cvt.u32.u64 %0, t; }" : "=r"(a) : "l"(p));
    return a;
}
static __device__ __forceinline__ uint32_t sw128(uint32_t off) {
    return off ^ ((off >> 3) & 0x70);
}
static __device__ __forceinline__ void ldsm_x4(uint32_t* r, uint32_t addr) {
    asm volatile("ldmatrix.sync.aligned.m8n8.x4.shared.b16 {%0,%1,%2,%3}, [%4];"
        : "=r"(r[0]), "=r"(r[1]), "=r"(r[2]), "=r"(r[3]) : "r"(addr));
}
static __device__ __forceinline__ void mma_bf16(float* c, const uint32_t* a, const uint32_t* b) {
    asm volatile("mma.sync.aligned.m16n8k16.row.col.f32.bf16.bf16.f32 "
        "{%0,%1,%2,%3}, {%4,%5,%6,%7}, {%8,%9}, {%0,%1,%2,%3};"
        : "+f"(c[0]), "+f"(c[1]), "+f"(c[2]), "+f"(c[3])
        : "r"(a[0]), "r"(a[1]), "r"(a[2]), "r"(a[3]), "r"(b[0]), "r"(b[1]));
}
#define CP_ASYNC16(dst, src) asm volatile("cp.async.cg.shared.global [%0], [%1], 16;" :: "r"(dst), "l"(src))
#define CP_COMMIT()          asm volatile("cp.async.commit_group;" ::: "memory")
#define CP_WAIT(n)           asm volatile("cp.async.wait_group %0;" :: "n"(n) : "memory")

static __device__ __forceinline__ void split4(float4 v, uint32_t& h01, uint32_t& h23,
                                              uint32_t& l01, uint32_t& l23) {
    __nv_bfloat162 H01 = __floats2bfloat162_rn(v.x, v.y);
    __nv_bfloat162 H23 = __floats2bfloat162_rn(v.z, v.w);
    float2 f01 = __bfloat1622float2(H01);
    float2 f23 = __bfloat1622float2(H23);
    __nv_bfloat162 L01 = __floats2bfloat162_rn(v.x - f01.x, v.y - f01.y);
    __nv_bfloat162 L23 = __floats2bfloat162_rn(v.z - f23.x, v.w - f23.y);
    h01 = *reinterpret_cast<uint32_t*>(&H01);
    h23 = *reinterpret_cast<uint32_t*>(&H23);
    l01 = *reinterpret_cast<uint32_t*>(&L01);
    l23 = *reinterpret_cast<uint32_t*>(&L23);
}

static __device__ __forceinline__ float fast_sig(float x)  { return 1.0f / (1.0f + __expf(-x)); }
static __device__ __forceinline__ float fast_tanh(float x) { float e = __expf(2.0f * x); return 1.0f - 2.0f / (e + 1.0f); }

__global__ __launch_bounds__(256)
void convert_kernel(const float* __restrict__ X, const float* __restrict__ Hs, GateParams gp)
{
    const int row = blockIdx.x;
    const int t   = threadIdx.x;

    const float* src;
    if (row < 4096)       src = X  + (size_t)row * 1024;
    else if (row < 8192)  src = Hs + (size_t)(row - 4096) * 1024;
    else {
        int r2  = row - 8192;
        int seg = r2 >> 12;
        int g   = (r2 >> 10) & 3;
        int hh  = r2 & 1023;
        src = (seg ? gp.u[g] : gp.w[g]) + (size_t)hh * 1024;
    }

    float4 v = *reinterpret_cast<const float4*>(src + t * 4);
    uint32_t h01, h23, l01, l23;
    split4(v, h01, h23, l01, l23);

    unsigned char* dst = g_scr + (size_t)row * 4096;
    const int kc  = t >> 3;
    const int blk = t & 7;
    *reinterpret_cast<uint2*>(dst + kc * 128 + blk * 8)      = make_uint2(h01, h23);
    *reinterpret_cast<uint2*>(dst + kc * 128 + 64 + blk * 8) = make_uint2(l01, l23);
}

__global__ __launch_bounds__(THREADS, 2)
void lstm_hmma_kernel(const float* __restrict__ oldc, GateParams gp,
                      float* __restrict__ outh, float* __restrict__ outc)
{
    extern __shared__ char dyn_raw[];
    char* dyn = (char*)(((uintptr_t)dyn_raw + 1023) & ~(uintptr_t)1023);
    __shared__ float bias_sm[64];

    const int tid  = threadIdx.x;
    const int lane = tid & 31;
    const int warp = tid >> 5;
    const int wm   = warp >> 1;          // 0..3 : 32 m-rows each
    const int wn   = warp & 1;           // 0..1 : 32 n-cols each
    const int h0   = blockIdx.x * 16;    // 64 h-tiles of 16
    const int m0   = blockIdx.y * 128;   // 32 m-tiles

    if (tid < 64) bias_sm[tid] = gp.b[tid >> 4][h0 + (tid & 15)];

    const int colf4  = tid & 7;     // 16B block within 128B row
    const int rowgrp = tid >> 3;    // 0..31

    const uint32_t sm_base = smem_u32(dyn);
    const uint32_t arow_b = (uint32_t)((wm * 32 + (lane & 15)) * 128) + ((lane >> 4) << 4);
    const uint32_t brow_b = (uint32_t)((wn * 32 + ((lane >> 4) << 3) + (lane & 7)) * 128) + (((lane >> 3) & 1) << 4);

    uint32_t tdst[4];
    #pragma unroll
    for (int i = 0; i < 4; i++)
        tdst[i] = sw128((uint32_t)((rowgrp + 32 * i) * 128 + colf4 * 16));

    // B scratch row components (rows of B tile: n = gate*16 + hh)
    const int bgate0 = rowgrp >> 4;          // gate of row rowgrp (i=0); i adds 2
    const int bhh    = rowgrp & 15;

    auto issue_chunk = [&](int c, uint32_t bufsm) {
        const int seg = c >> 5;
        const int kc  = c & 31;
        const unsigned char* abase = g_scr + ((size_t)(seg * 4096 + m0 + rowgrp)) * 4096 + kc * 128 + colf4 * 16;
        #pragma unroll
        for (int i = 0; i < 4; i++)
            CP_ASYNC16(bufsm + tdst[i], abase + (size_t)i * 32 * 4096);
        #pragma unroll
        for (int i = 0; i < 2; i++) {
            const size_t brow = (size_t)(8192 + seg * 4096 + (bgate0 + 2 * i) * 1024 + h0 + bhh);
            CP_ASYNC16(bufsm + A_STAGE_BYTES + tdst[i],
                       g_scr + brow * 4096 + kc * 128 + colf4 * 16);
        }
    };

    float acc[2][4][4];
    #pragma unroll
    for (int mt = 0; mt < 2; mt++)
        #pragma unroll
        for (int nt = 0; nt < 4; nt++)
            #pragma unroll
            for (int q = 0; q < 4; q++) acc[mt][nt][q] = 0.0f;

    #pragma unroll
    for (int p = 0; p < STAGES - 1; p++) {
        issue_chunk(p, sm_base + p * STAGE_BYTES);
        CP_COMMIT();
    }
    CP_WAIT(STAGES - 2);
    __syncthreads();

    int buf = 0;
    for (int c = 0; c < NCHUNK; c++) {
        int nc2 = c + STAGES - 1;
        if (nc2 < NCHUNK) {
            int nb = buf + STAGES - 1; if (nb >= STAGES) nb -= STAGES;
            issue_chunk(nc2, sm_base + nb * STAGE_BYTES);
        }
        CP_COMMIT();

        // compute 32-K chunk: preload fragments for both k16 steps, then MMA
        {
            const uint32_t stA = sm_base + buf * STAGE_BYTES;
            const uint32_t stB = stA + A_STAGE_BYTES;
            uint32_t ah[2][2][4], al[2][2][4], bh[2][4][2], bl[2][4][2];
            #pragma unroll
            for (int ks = 0; ks < 2; ks++) {
                #pragma unroll
                for (int mt = 0; mt < 2; mt++) {
                    uint32_t off = arow_b + (uint32_t)(mt * 2048 + ks * 32);
                    ldsm_x4(ah[ks][mt], stA + sw128(off));
                    ldsm_x4(al[ks][mt], stA + sw128(off + 64));
                }
                #pragma unroll
                for (int nt2 = 0; nt2 < 2; nt2++) {
                    uint32_t off = brow_b + (uint32_t)(nt2 * 2048 + ks * 32);
                    uint32_t r[4];
                    ldsm_x4(r, stB + sw128(off));
                    bh[ks][nt2*2][0] = r[0]; bh[ks][nt2*2][1] = r[1];
                    bh[ks][nt2*2+1][0] = r[2]; bh[ks][nt2*2+1][1] = r[3];
                    ldsm_x4(r, stB + sw128(off + 64));
                    bl[ks][nt2*2][0] = r[0]; bl[ks][nt2*2][1] = r[1];
                    bl[ks][nt2*2+1][0] = r[2]; bl[ks][nt2*2+1][1] = r[3];
                }
            }
            #pragma unroll
            for (int ks = 0; ks < 2; ks++)
                #pragma unroll
                for (int mt = 0; mt < 2; mt++)
                    #pragma unroll
                    for (int nt = 0; nt < 4; nt++) {
                        mma_bf16(acc[mt][nt], ah[ks][mt], bh[ks][nt]);
                        mma_bf16(acc[mt][nt], ah[ks][mt], bl[ks][nt]);
                        mma_bf16(acc[mt][nt], al[ks][mt], bh[ks][nt]);
                    }
        }

        CP_WAIT(STAGES - 2);
        __syncthreads();
        if (++buf == STAGES) buf = 0;
    }

    // ---- epilogue: accs -> smem transpose [n][m], then fused LSTM ----
    float* Csm = reinterpret_cast<float*>(dyn);   // [64][129] floats (33 KB)
    {
        const int gid = lane >> 2;
        const int tig = lane & 3;
        #pragma unroll
        for (int mt = 0; mt < 2; mt++)
            #pragma unroll
            for (int nt = 0; nt < 4; nt++) {
                int row = wm * 32 + mt * 16 + gid;
                int col = wn * 32 + nt * 8 + tig * 2;
                Csm[(col    ) * 129 + row    ] = acc[mt][nt][0];
                Csm[(col + 1) * 129 + row    ] = acc[mt][nt][1];
                Csm[(col    ) * 129 + row + 8] = acc[mt][nt][2];
                Csm[(col + 1) * 129 + row + 8] = acc[mt][nt][3];
            }
    }
    __syncthreads();

    #pragma unroll
    for (int it = 0; it < 8; it++) {
        int idx = tid + it * 256;           // 2048 = 128 m x 16 hh
        int hh = idx & 15;
        int m  = idx >> 4;
        float gi = Csm[( 0 + hh) * 129 + m] + bias_sm[ 0 + hh];
        float go = Csm[(16 + hh) * 129 + m] + bias_sm[16 + hh];
        float gf = Csm[(32 + hh) * 129 + m] + bias_sm[32 + hh];
        float gc = Csm[(48 + hh) * 129 + m] + bias_sm[48 + hh];
        size_t g = (size_t)(m0 + m) * 1024 + h0 + hh;
        float ig = fast_sig(gi);
        float og = fast_sig(go);
        float fg = fast_sig(gf);
        float ct = fast_tanh(gc);
        float nc = fg * oldc[g] + ig * ct;
        outh[g] = og * fast_tanh(nc);
        outc[g] = nc;
    }
}

extern "C" void kernel_launch(void* const* d_in, const int* in_sizes, int n_in,
                              void* d_out, int out_size)
{
    const float* incoming = (const float*)d_in[0];
    const float* old_h    = (const float*)d_in[1];
    const float* old_c    = (const float*)d_in[2];

    GateParams gp;
    gp.w[0] = (const float*)d_in[3];  gp.b[0] = (const float*)d_in[4];  gp.u[0] = (const float*)d_in[5];
    gp.w[1] = (const float*)d_in[6];  gp.b[1] = (const float*)d_in[7];  gp.u[1] = (const float*)d_in[8];
    gp.w[2] = (const float*)d_in[9];  gp.b[2] = (const float*)d_in[10]; gp.u[2] = (const float*)d_in[11];
    gp.w[3] = (const float*)d_in[12]; gp.b[3] = (const float*)d_in[13]; gp.u[3] = (const float*)d_in[14];

    float* out_h = (float*)d_out;
    float* out_c = out_h + (size_t)BATCHSZ * HID;

    convert_kernel<<<16384, 256>>>(incoming, old_h, gp);

    cudaFuncSetAttribute(lstm_hmma_kernel, cudaFuncAttributeMaxDynamicSharedMemorySize, DYN_BYTES);
    dim3 grid(HID / 16, BATCHSZ / 128);   // 64 x 32 = 2048 CTAs
    lstm_hmma_kernel<<<grid, THREADS, DYN_BYTES>>>(old_c, gp, out_h, out_c);
}

// round 8
// speedup vs baseline: 6.0766x; 1.9101x over previous
#include <cuda_runtime.h>
#include <cuda_fp16.h>
#include <cstdint>

// LSTMCell fused, two kernels:
//  1) convert_kernel: fp32 -> fp16 (rn) of X,H,W,U into a __device__ scratch
//     laid out exactly as the GEMM smem tiles (128B row = 64 fp16 K-values).
//  2) lstm_hmma_kernel: single-term fp16 mma.sync GEMM, fp32 accumulate,
//     cp.async 4-stage ring, 2 CTAs/SM, fused LSTM epilogue.
// B=4096, I=H=1024. CTA tile M=128 x N=64 (16 h x 4 gates), grid 2048.
// K = 2048, chunks of 64 (one 128B scratch block per row per chunk).

#define HID     1024
#define BATCHSZ 4096
#define NCHUNK  32          // 2048 / 64
#define THREADS 256
#define STAGES  4

#define A_STAGE_BYTES (128*128)                 // 16 KB (128 rows x 64 fp16)
#define B_STAGE_BYTES (64*128)                  // 8 KB
#define STAGE_BYTES   (A_STAGE_BYTES + B_STAGE_BYTES)   // 24 KB
#define DYN_BYTES     (STAGES*STAGE_BYTES + 1024)       // 97 KB -> 2 CTAs/SM

// Scratch: 16384 rows x 2048 B (fp16).
// rows [0,4096): X | [4096,8192): H
// rows [8192,16384): 8192 + seg*4096 + gate*1024 + h   (seg 0 = W, 1 = U)
__device__ __align__(128) unsigned char g_scr[(size_t)16384 * 2048];

struct GateParams { const float* w[4]; const float* u[4]; const float* b[4]; };

static __device__ __forceinline__ uint32_t smem_u32(const void* p) {
    uint32_t a;
    asm("{ .reg .u64 t; cvta.to.shared.u64 t, %1; cvt.u32.u64 %0, t; }" : "=r"(a) : "l"(p));
    return a;
}
static __device__ __forceinline__ uint32_t sw128(uint32_t off) {
    return off ^ ((off >> 3) & 0x70);
}
static __device__ __forceinline__ void ldsm_x4(uint32_t* r, uint32_t addr) {
    asm volatile("ldmatrix.sync.aligned.m8n8.x4.shared.b16 {%0,%1,%2,%3}, [%4];"
        : "=r"(r[0]), "=r"(r[1]), "=r"(r[2]), "=r"(r[3]) : "r"(addr));
}
static __device__ __forceinline__ void mma_f16(float* c, const uint32_t* a, const uint32_t* b) {
    asm volatile("mma.sync.aligned.m16n8k16.row.col.f32.f16.f16.f32 "
        "{%0,%1,%2,%3}, {%4,%5,%6,%7}, {%8,%9}, {%0,%1,%2,%3};"
        : "+f"(c[0]), "+f"(c[1]), "+f"(c[2]), "+f"(c[3])
        : "r"(a[0]), "r"(a[1]), "r"(a[2]), "r"(a[3]), "r"(b[0]), "r"(b[1]));
}
#define CP_ASYNC16(dst, src) asm volatile("cp.async.cg.shared.global [%0], [%1], 16;" :: "r"(dst), "l"(src))
#define CP_COMMIT()          asm volatile("cp.async.commit_group;" ::: "memory")
#define CP_WAIT(n)           asm volatile("cp.async.wait_group %0;" :: "n"(n) : "memory")

static __device__ __forceinline__ float fast_sig(float x)  { return 1.0f / (1.0f + __expf(-x)); }
static __device__ __forceinline__ float fast_tanh(float x) { float e = __expf(2.0f * x); return 1.0f - 2.0f / (e + 1.0f); }

// ---- pre-pass: one block per scratch row (1024 floats -> 1024 fp16)
__global__ __launch_bounds__(256)
void convert_kernel(const float* __restrict__ X, const float* __restrict__ Hs, GateParams gp)
{
    const int row = blockIdx.x;
    const int t   = threadIdx.x;

    const float* src;
    if (row < 4096)       src = X  + (size_t)row * 1024;
    else if (row < 8192)  src = Hs + (size_t)(row - 4096) * 1024;
    else {
        int r2  = row - 8192;
        int seg = r2 >> 12;
        int g   = (r2 >> 10) & 3;
        int hh  = r2 & 1023;
        src = (seg ? gp.u[g] : gp.w[g]) + (size_t)hh * 1024;
    }

    float4 v = *reinterpret_cast<const float4*>(src + t * 4);
    __half2 p01 = __floats2half2_rn(v.x, v.y);
    __half2 p23 = __floats2half2_rn(v.z, v.w);

    unsigned char* dst = g_scr + (size_t)row * 2048;
    // element index e = 4t; 64 elems (128B) per K-chunk block
    *reinterpret_cast<uint2*>(dst + (t >> 4) * 128 + (t & 15) * 8) =
        make_uint2(*reinterpret_cast<uint32_t*>(&p01), *reinterpret_cast<uint32_t*>(&p23));
}

__global__ __launch_bounds__(THREADS, 2)
void lstm_hmma_kernel(const float* __restrict__ oldc, GateParams gp,
                      float* __restrict__ outh, float* __restrict__ outc)
{
    extern __shared__ char dyn_raw[];
    char* dyn = (char*)(((uintptr_t)dyn_raw + 1023) & ~(uintptr_t)1023);
    __shared__ float bias_sm[64];

    const int tid  = threadIdx.x;
    const int lane = tid & 31;
    const int warp = tid >> 5;
    const int wm   = warp >> 1;          // 0..3 : 32 m-rows each
    const int wn   = warp & 1;           // 0..1 : 32 n-cols each
    const int h0   = blockIdx.x * 16;    // 64 h-tiles of 16
    const int m0   = blockIdx.y * 128;   // 32 m-tiles

    if (tid < 64) bias_sm[tid] = gp.b[tid >> 4][h0 + (tid & 15)];

    const int colf4  = tid & 7;     // 16B block within 128B row
    const int rowgrp = tid >> 3;    // 0..31

    const uint32_t sm_base = smem_u32(dyn);
    const uint32_t arow_b = (uint32_t)((wm * 32 + (lane & 15)) * 128) + ((lane >> 4) << 4);
    const uint32_t brow_b = (uint32_t)((wn * 32 + ((lane >> 4) << 3) + (lane & 7)) * 128) + (((lane >> 3) & 1) << 4);

    uint32_t tdst[4];
    #pragma unroll
    for (int i = 0; i < 4; i++)
        tdst[i] = sw128((uint32_t)((rowgrp + 32 * i) * 128 + colf4 * 16));

    // B scratch row components (rows of B tile: n = gate*16 + hh)
    const int bgate0 = rowgrp >> 4;          // gate of row rowgrp; i adds 2
    const int bhh    = rowgrp & 15;

    auto issue_chunk = [&](int c, uint32_t bufsm) {
        const int seg = c >> 4;
        const int kc  = c & 15;
        const unsigned char* abase = g_scr + ((size_t)(seg * 4096 + m0 + rowgrp)) * 2048 + kc * 128 + colf4 * 16;
        #pragma unroll
        for (int i = 0; i < 4; i++)
            CP_ASYNC16(bufsm + tdst[i], abase + (size_t)i * 32 * 2048);
        #pragma unroll
        for (int i = 0; i < 2; i++) {
            const size_t brow = (size_t)(8192 + seg * 4096 + (bgate0 + 2 * i) * 1024 + h0 + bhh);
            CP_ASYNC16(bufsm + A_STAGE_BYTES + tdst[i],
                       g_scr + brow * 2048 + kc * 128 + colf4 * 16);
        }
    };

    float acc[2][4][4];
    #pragma unroll
    for (int mt = 0; mt < 2; mt++)
        #pragma unroll
        for (int nt = 0; nt < 4; nt++)
            #pragma unroll
            for (int q = 0; q < 4; q++) acc[mt][nt][q] = 0.0f;

    #pragma unroll
    for (int p = 0; p < STAGES - 1; p++) {
        issue_chunk(p, sm_base + p * STAGE_BYTES);
        CP_COMMIT();
    }
    CP_WAIT(STAGES - 2);
    __syncthreads();

    int buf = 0;
    for (int c = 0; c < NCHUNK; c++) {
        int nc2 = c + STAGES - 1;
        if (nc2 < NCHUNK) {
            int nb = buf + STAGES - 1; if (nb >= STAGES) nb -= STAGES;
            issue_chunk(nc2, sm_base + nb * STAGE_BYTES);
        }
        CP_COMMIT();

        // compute 64-K chunk: 4 k16 steps
        {
            const uint32_t stA = sm_base + buf * STAGE_BYTES;
            const uint32_t stB = stA + A_STAGE_BYTES;
            #pragma unroll
            for (int ks = 0; ks < 4; ks++) {
                uint32_t ah[2][4], bb[4][2];
                #pragma unroll
                for (int mt = 0; mt < 2; mt++)
                    ldsm_x4(ah[mt], stA + sw128(arow_b + (uint32_t)(mt * 2048 + ks * 32)));
                #pragma unroll
                for (int nt2 = 0; nt2 < 2; nt2++) {
                    uint32_t r[4];
                    ldsm_x4(r, stB + sw128(brow_b + (uint32_t)(nt2 * 2048 + ks * 32)));
                    bb[nt2*2][0] = r[0]; bb[nt2*2][1] = r[1];
                    bb[nt2*2+1][0] = r[2]; bb[nt2*2+1][1] = r[3];
                }
                #pragma unroll
                for (int mt = 0; mt < 2; mt++)
                    #pragma unroll
                    for (int nt = 0; nt < 4; nt++)
                        mma_f16(acc[mt][nt], ah[mt], bb[nt]);
            }
        }

        CP_WAIT(STAGES - 2);
        __syncthreads();
        if (++buf == STAGES) buf = 0;
    }

    // ---- epilogue: accs -> smem transpose [n][m], then fused LSTM ----
    float* Csm = reinterpret_cast<float*>(dyn);   // [64][129] floats (33 KB)
    {
        const int gid = lane >> 2;
        const int tig = lane & 3;
        #pragma unroll
        for (int mt = 0; mt < 2; mt++)
            #pragma unroll
            for (int nt = 0; nt < 4; nt++) {
                int row = wm * 32 + mt * 16 + gid;
                int col = wn * 32 + nt * 8 + tig * 2;
                Csm[(col    ) * 129 + row    ] = acc[mt][nt][0];
                Csm[(col + 1) * 129 + row    ] = acc[mt][nt][1];
                Csm[(col    ) * 129 + row + 8] = acc[mt][nt][2];
                Csm[(col + 1) * 129 + row + 8] = acc[mt][nt][3];
            }
    }
    __syncthreads();

    #pragma unroll
    for (int it = 0; it < 8; it++) {
        int idx = tid + it * 256;           // 2048 = 128 m x 16 hh
        int hh = idx & 15;
        int m  = idx >> 4;
        float gi = Csm[( 0 + hh) * 129 + m] + bias_sm[ 0 + hh];
        float go = Csm[(16 + hh) * 129 + m] + bias_sm[16 + hh];
        float gf = Csm[(32 + hh) * 129 + m] + bias_sm[32 + hh];
        float gc = Csm[(48 + hh) * 129 + m] + bias_sm[48 + hh];
        size_t g = (size_t)(m0 + m) * 1024 + h0 + hh;
        float ig = fast_sig(gi);
        float og = fast_sig(go);
        float fg = fast_sig(gf);
        float ct = fast_tanh(gc);
        float nc = fg * oldc[g] + ig * ct;
        outh[g] = og * fast_tanh(nc);
        outc[g] = nc;
    }
}

extern "C" void kernel_launch(void* const* d_in, const int* in_sizes, int n_in,
                              void* d_out, int out_size)
{
    const float* incoming = (const float*)d_in[0];
    const float* old_h    = (const float*)d_in[1];
    const float* old_c    = (const float*)d_in[2];

    GateParams gp;
    gp.w[0] = (const float*)d_in[3];  gp.b[0] = (const float*)d_in[4];  gp.u[0] = (const float*)d_in[5];
    gp.w[1] = (const float*)d_in[6];  gp.b[1] = (const float*)d_in[7];  gp.u[1] = (const float*)d_in[8];
    gp.w[2] = (const float*)d_in[9];  gp.b[2] = (const float*)d_in[10]; gp.u[2] = (const float*)d_in[11];
    gp.w[3] = (const float*)d_in[12]; gp.b[3] = (const float*)d_in[13]; gp.u[3] = (const float*)d_in[14];

    float* out_h = (float*)d_out;
    float* out_c = out_h + (size_t)BATCHSZ * HID;

    convert_kernel<<<16384, 256>>>(incoming, old_h, gp);

    cudaFuncSetAttribute(lstm_hmma_kernel, cudaFuncAttributeMaxDynamicSharedMemorySize, DYN_BYTES);
    dim3 grid(HID / 16, BATCHSZ / 128);   // 64 x 32 = 2048 CTAs
    lstm_hmma_kernel<<<grid, THREADS, DYN_BYTES>>>(old_c, gp, out_h, out_c);
}

// round 9
// speedup vs baseline: 7.0366x; 1.1580x over previous
#include <cuda_runtime.h>
#include <cuda_fp16.h>
#include <cstdint>

// LSTMCell fused, two kernels:
//  1) convert_kernel: fp32 -> fp16 (rn) of X,H,W,U into a __device__ scratch
//     laid out exactly as the GEMM smem tiles (128B row = 64 fp16 K-values).
//  2) lstm_hmma_kernel: single-term fp16 mma.sync GEMM, fp32 accumulate,
//     cp.async 3-stage ring, 2 CTAs/SM, fused LSTM epilogue.
// B=4096, I=H=1024. CTA tile M=128 x N=128 (32 h x 4 gates), warp tile 64x32
// (warp grid 2x4 -> A dup 4, B dup 2 = min smem read traffic per HMMA).
// K = 2048, chunks of 64.

#define HID     1024
#define BATCHSZ 4096
#define NCHUNK  32          // 2048 / 64
#define THREADS 256
#define STAGES  3

#define A_STAGE_BYTES (128*128)                 // 16 KB (128 rows x 64 fp16)
#define B_STAGE_BYTES (128*128)                 // 16 KB
#define STAGE_BYTES   (A_STAGE_BYTES + B_STAGE_BYTES)   // 32 KB
#define DYN_BYTES     (STAGES*STAGE_BYTES + 1024)       // 97 KB -> 2 CTAs/SM

// Scratch: 16384 rows x 2048 B (fp16).
// rows [0,4096): X | [4096,8192): H
// rows [8192,16384): 8192 + seg*4096 + gate*1024 + h   (seg 0 = W, 1 = U)
__device__ __align__(128) unsigned char g_scr[(size_t)16384 * 2048];

struct GateParams { const float* w[4]; const float* u[4]; const float* b[4]; };

static __device__ __forceinline__ uint32_t smem_u32(const void* p) {
    uint32_t a;
    asm("{ .reg .u64 t; cvta.to.shared.u64 t, %1; cvt.u32.u64 %0, t; }" : "=r"(a) : "l"(p));
    return a;
}
static __device__ __forceinline__ uint32_t sw128(uint32_t off) {
    return off ^ ((off >> 3) & 0x70);
}
static __device__ __forceinline__ void ldsm_x4(uint32_t* r, uint32_t addr) {
    asm volatile("ldmatrix.sync.aligned.m8n8.x4.shared.b16 {%0,%1,%2,%3}, [%4];"
        : "=r"(r[0]), "=r"(r[1]), "=r"(r[2]), "=r"(r[3]) : "r"(addr));
}
static __device__ __forceinline__ void mma_f16(float* c, const uint32_t* a, const uint32_t* b) {
    asm volatile("mma.sync.aligned.m16n8k16.row.col.f32.f16.f16.f32 "
        "{%0,%1,%2,%3}, {%4,%5,%6,%7}, {%8,%9}, {%0,%1,%2,%3};"
        : "+f"(c[0]), "+f"(c[1]), "+f"(c[2]), "+f"(c[3])
        : "r"(a[0]), "r"(a[1]), "r"(a[2]), "r"(a[3]), "r"(b[0]), "r"(b[1]));
}
#define CP_ASYNC16(dst, src) asm volatile("cp.async.cg.shared.global [%0], [%1], 16;" :: "r"(dst), "l"(src))
#define CP_COMMIT()          asm volatile("cp.async.commit_group;" ::: "memory")
#define CP_WAIT(n)           asm volatile("cp.async.wait_group %0;" :: "n"(n) : "memory")

static __device__ __forceinline__ float fast_sig(float x)  { return 1.0f / (1.0f + __expf(-x)); }
static __device__ __forceinline__ float fast_tanh(float x) { float e = __expf(2.0f * x); return 1.0f - 2.0f / (e + 1.0f); }

// ---- pre-pass: one block per scratch row (1024 floats -> 1024 fp16)
__global__ __launch_bounds__(256)
void convert_kernel(const float* __restrict__ X, const float* __restrict__ Hs, GateParams gp)
{
    const int row = blockIdx.x;
    const int t   = threadIdx.x;

    const float* src;
    if (row < 4096)       src = X  + (size_t)row * 1024;
    else if (row < 8192)  src = Hs + (size_t)(row - 4096) * 1024;
    else {
        int r2  = row - 8192;
        int seg = r2 >> 12;
        int g   = (r2 >> 10) & 3;
        int hh  = r2 & 1023;
        src = (seg ? gp.u[g] : gp.w[g]) + (size_t)hh * 1024;
    }

    float4 v = *reinterpret_cast<const float4*>(src + t * 4);
    __half2 p01 = __floats2half2_rn(v.x, v.y);
    __half2 p23 = __floats2half2_rn(v.z, v.w);

    unsigned char* dst = g_scr + (size_t)row * 2048;
    *reinterpret_cast<uint2*>(dst + (t >> 4) * 128 + (t & 15) * 8) =
        make_uint2(*reinterpret_cast<uint32_t*>(&p01), *reinterpret_cast<uint32_t*>(&p23));
}

__global__ __launch_bounds__(THREADS, 2)
void lstm_hmma_kernel(const float* __restrict__ oldc, GateParams gp,
                      float* __restrict__ outh, float* __restrict__ outc)
{
    extern __shared__ char dyn_raw[];
    char* dyn = (char*)(((uintptr_t)dyn_raw + 1023) & ~(uintptr_t)1023);
    __shared__ float bias_sm[128];

    const int tid  = threadIdx.x;
    const int lane = tid & 31;
    const int warp = tid >> 5;
    const int wm   = warp >> 2;          // 0..1 : 64 m-rows each
    const int wn   = warp & 3;           // 0..3 : 32 n-cols each
    const int h0   = blockIdx.x * 32;    // 32 h-tiles of 32
    const int m0   = blockIdx.y * 128;   // 32 m-tiles

    if (tid < 128) bias_sm[tid] = gp.b[tid >> 5][h0 + (tid & 31)];

    const int colf4  = tid & 7;     // 16B block within 128B row
    const int rowgrp = tid >> 3;    // 0..31; handles rows rowgrp+32i

    const uint32_t sm_base = smem_u32(dyn);
    const uint32_t arow_b = (uint32_t)((wm * 64 + (lane & 15)) * 128) + ((lane >> 4) << 4);
    const uint32_t brow_b = (uint32_t)((wn * 32 + ((lane >> 4) << 3) + (lane & 7)) * 128) + (((lane >> 3) & 1) << 4);

    uint32_t tdst[4];
    #pragma unroll
    for (int i = 0; i < 4; i++)
        tdst[i] = sw128((uint32_t)((rowgrp + 32 * i) * 128 + colf4 * 16));

    // B tile rows: n = gate*32 + hh; row rowgrp+32i -> gate i, hh = rowgrp.
    auto issue_chunk = [&](int c, uint32_t bufsm) {
        const int seg = c >> 4;
        const int kc  = c & 15;
        const unsigned char* abase = g_scr + ((size_t)(seg * 4096 + m0 + rowgrp)) * 2048 + kc * 128 + colf4 * 16;
        const unsigned char* bbase = g_scr + ((size_t)(8192 + seg * 4096 + h0 + rowgrp)) * 2048 + kc * 128 + colf4 * 16;
        #pragma unroll
        for (int i = 0; i < 4; i++) {
            CP_ASYNC16(bufsm + tdst[i], abase + (size_t)i * 32 * 2048);
            CP_ASYNC16(bufsm + A_STAGE_BYTES + tdst[i], bbase + (size_t)i * 1024 * 2048);
        }
    };

    float acc[4][4][4];
    #pragma unroll
    for (int mt = 0; mt < 4; mt++)
        #pragma unroll
        for (int nt = 0; nt < 4; nt++)
            #pragma unroll
            for (int q = 0; q < 4; q++) acc[mt][nt][q] = 0.0f;

    #pragma unroll
    for (int p = 0; p < STAGES - 1; p++) {
        issue_chunk(p, sm_base + p * STAGE_BYTES);
        CP_COMMIT();
    }
    CP_WAIT(STAGES - 2);
    __syncthreads();

    int buf = 0;
    for (int c = 0; c < NCHUNK; c++) {
        int nc2 = c + STAGES - 1;
        if (nc2 < NCHUNK) {
            int nb = buf + STAGES - 1; if (nb >= STAGES) nb -= STAGES;
            issue_chunk(nc2, sm_base + nb * STAGE_BYTES);
        }
        CP_COMMIT();

        // compute 64-K chunk: 4 k16 steps
        {
            const uint32_t stA = sm_base + buf * STAGE_BYTES;
            const uint32_t stB = stA + A_STAGE_BYTES;
            #pragma unroll
            for (int ks = 0; ks < 4; ks++) {
                uint32_t ah[4][4], bb[4][2];
                #pragma unroll
                for (int mt = 0; mt < 4; mt++)
                    ldsm_x4(ah[mt], stA + sw128(arow_b + (uint32_t)(mt * 2048 + ks * 32)));
                #pragma unroll
                for (int nt2 = 0; nt2 < 2; nt2++) {
                    uint32_t r[4];
                    ldsm_x4(r, stB + sw128(brow_b + (uint32_t)(nt2 * 2048 + ks * 32)));
                    bb[nt2*2][0] = r[0]; bb[nt2*2][1] = r[1];
                    bb[nt2*2+1][0] = r[2]; bb[nt2*2+1][1] = r[3];
                }
                #pragma unroll
                for (int mt = 0; mt < 4; mt++)
                    #pragma unroll
                    for (int nt = 0; nt < 4; nt++)
                        mma_f16(acc[mt][nt], ah[mt], bb[nt]);
            }
        }

        CP_WAIT(STAGES - 2);
        __syncthreads();
        if (++buf == STAGES) buf = 0;
    }

    // ---- epilogue: accs -> smem transpose [n][m], then fused LSTM ----
    float* Csm = reinterpret_cast<float*>(dyn);   // [128][129] floats (66 KB < 97 KB)
    {
        const int gid = lane >> 2;
        const int tig = lane & 3;
        #pragma unroll
        for (int mt = 0; mt < 4; mt++)
            #pragma unroll
            for (int nt = 0; nt < 4; nt++) {
                int row = wm * 64 + mt * 16 + gid;
                int col = wn * 32 + nt * 8 + tig * 2;
                Csm[(col    ) * 129 + row    ] = acc[mt][nt][0];
                Csm[(col + 1) * 129 + row    ] = acc[mt][nt][1];
                Csm[(col    ) * 129 + row + 8] = acc[mt][nt][2];
                Csm[(col + 1) * 129 + row + 8] = acc[mt][nt][3];
            }
    }
    __syncthreads();

    #pragma unroll
    for (int it = 0; it < 16; it++) {
        int idx = tid + it * 256;           // 4096 = 128 m x 32 hh
        int hh = idx & 31;
        int m  = idx >> 5;
        float gi = Csm[( 0 + hh) * 129 + m] + bias_sm[ 0 + hh];
        float go = Csm[(32 + hh) * 129 + m] + bias_sm[32 + hh];
        float gf = Csm[(64 + hh) * 129 + m] + bias_sm[64 + hh];
        float gc = Csm[(96 + hh) * 129 + m] + bias_sm[96 + hh];
        size_t g = (size_t)(m0 + m) * 1024 + h0 + hh;
        float ig = fast_sig(gi);
        float og = fast_sig(go);
        float fg = fast_sig(gf);
        float ct = fast_tanh(gc);
        float nc = fg * oldc[g] + ig * ct;
        outh[g] = og * fast_tanh(nc);
        outc[g] = nc;
    }
}

extern "C" void kernel_launch(void* const* d_in, const int* in_sizes, int n_in,
                              void* d_out, int out_size)
{
    const float* incoming = (const float*)d_in[0];
    const float* old_h    = (const float*)d_in[1];
    const float* old_c    = (const float*)d_in[2];

    GateParams gp;
    gp.w[0] = (const float*)d_in[3];  gp.b[0] = (const float*)d_in[4];  gp.u[0] = (const float*)d_in[5];
    gp.w[1] = (const float*)d_in[6];  gp.b[1] = (const float*)d_in[7];  gp.u[1] = (const float*)d_in[8];
    gp.w[2] = (const float*)d_in[9];  gp.b[2] = (const float*)d_in[10]; gp.u[2] = (const float*)d_in[11];
    gp.w[3] = (const float*)d_in[12]; gp.b[3] = (const float*)d_in[13]; gp.u[3] = (const float*)d_in[14];

    float* out_h = (float*)d_out;
    float* out_c = out_h + (size_t)BATCHSZ * HID;

    convert_kernel<<<16384, 256>>>(incoming, old_h, gp);

    cudaFuncSetAttribute(lstm_hmma_kernel, cudaFuncAttributeMaxDynamicSharedMemorySize, DYN_BYTES);
    dim3 grid(HID / 32, BATCHSZ / 128);   // 32 x 32 = 1024 CTAs
    lstm_hmma_kernel<<<grid, THREADS, DYN_BYTES>>>(old_c, gp, out_h, out_c);
}

// round 10
// speedup vs baseline: 7.7766x; 1.1052x over previous
#include <cuda_runtime.h>
#include <cuda_fp16.h>
#include <cstdint>

// LSTMCell fused, two kernels:
//  1) convert_kernel: fp32 -> fp16 (rn) of X,H,W,U into a __device__ scratch
//     laid out exactly as the GEMM smem tiles (128B row = 64 fp16 K-values).
//     MLP-8 version: 1024 blocks x 256 thr, 16 rows/block, 8 loads in flight.
//  2) lstm_hmma_kernel: single-term fp16 mma.sync GEMM, fp32 accumulate,
//     cp.async 3-stage ring, 2 CTAs/SM, fused LSTM epilogue. (unchanged R9)
// B=4096, I=H=1024. CTA tile M=128 x N=128 (32 h x 4 gates), warp tile 64x32.

#define HID     1024
#define BATCHSZ 4096
#define NCHUNK  32          // 2048 / 64
#define THREADS 256
#define STAGES  3

#define A_STAGE_BYTES (128*128)                 // 16 KB (128 rows x 64 fp16)
#define B_STAGE_BYTES (128*128)                 // 16 KB
#define STAGE_BYTES   (A_STAGE_BYTES + B_STAGE_BYTES)   // 32 KB
#define DYN_BYTES     (STAGES*STAGE_BYTES + 1024)       // 97 KB -> 2 CTAs/SM

// Scratch: 16384 rows x 2048 B (fp16).
// rows [0,4096): X | [4096,8192): H
// rows [8192,16384): 8192 + seg*4096 + gate*1024 + h   (seg 0 = W, 1 = U)
__device__ __align__(128) unsigned char g_scr[(size_t)16384 * 2048];

struct GateParams { const float* w[4]; const float* u[4]; const float* b[4]; };

static __device__ __forceinline__ uint32_t smem_u32(const void* p) {
    uint32_t a;
    asm("{ .reg .u64 t; cvta.to.shared.u64 t, %1; cvt.u32.u64 %0, t; }" : "=r"(a) : "l"(p));
    return a;
}
static __device__ __forceinline__ uint32_t sw128(uint32_t off) {
    return off ^ ((off >> 3) & 0x70);
}
static __device__ __forceinline__ void ldsm_x4(uint32_t* r, uint32_t addr) {
    asm volatile("ldmatrix.sync.aligned.m8n8.x4.shared.b16 {%0,%1,%2,%3}, [%4];"
        : "=r"(r[0]), "=r"(r[1]), "=r"(r[2]), "=r"(r[3]) : "r"(addr));
}
static __device__ __forceinline__ void mma_f16(float* c, const uint32_t* a, const uint32_t* b) {
    asm volatile("mma.sync.aligned.m16n8k16.row.col.f32.f16.f16.f32 "
        "{%0,%1,%2,%3}, {%4,%5,%6,%7}, {%8,%9}, {%0,%1,%2,%3};"
        : "+f"(c[0]), "+f"(c[1]), "+f"(c[2]), "+f"(c[3])
        : "r"(a[0]), "r"(a[1]), "r"(a[2]), "r"(a[3]), "r"(b[0]), "r"(b[1]));
}
#define CP_ASYNC16(dst, src) asm volatile("cp.async.cg.shared.global [%0], [%1], 16;" :: "r"(dst), "l"(src))
#define CP_COMMIT()          asm volatile("cp.async.commit_group;" ::: "memory")
#define CP_WAIT(n)           asm volatile("cp.async.wait_group %0;" :: "n"(n) : "memory")

static __device__ __forceinline__ float fast_sig(float x)  { return 1.0f / (1.0f + __expf(-x)); }
static __device__ __forceinline__ float fast_tanh(float x) { float e = __expf(2.0f * x); return 1.0f - 2.0f / (e + 1.0f); }

// ---- pre-pass: 1024 blocks x 256 thr; 16 rows per block, 8 rows per batch
//      -> 8 independent LDG.128 in flight per thread (MLP 8), single wave.
__global__ __launch_bounds__(256)
void convert_kernel(const float* __restrict__ X, const float* __restrict__ Hs, GateParams gp)
{
    const int t = threadIdx.x;

    #pragma unroll
    for (int b = 0; b < 2; b++) {
        float4 v[8];
        int rows[8];
        #pragma unroll
        for (int i = 0; i < 8; i++) {
            int row = blockIdx.x * 16 + b * 8 + i;
            rows[i] = row;
            const float* src;
            if (row < 4096)       src = X  + (size_t)row * 1024;
            else if (row < 8192)  src = Hs + (size_t)(row - 4096) * 1024;
            else {
                int r2  = row - 8192;
                int seg = r2 >> 12;
                int g   = (r2 >> 10) & 3;
                int hh  = r2 & 1023;
                src = (seg ? gp.u[g] : gp.w[g]) + (size_t)hh * 1024;
            }
            v[i] = *reinterpret_cast<const float4*>(src + t * 4);
        }
        #pragma unroll
        for (int i = 0; i < 8; i++) {
            __half2 p01 = __floats2half2_rn(v[i].x, v[i].y);
            __half2 p23 = __floats2half2_rn(v[i].z, v[i].w);
            unsigned char* dst = g_scr + (size_t)rows[i] * 2048;
            *reinterpret_cast<uint2*>(dst + (t >> 4) * 128 + (t & 15) * 8) =
                make_uint2(*reinterpret_cast<uint32_t*>(&p01),
                           *reinterpret_cast<uint32_t*>(&p23));
        }
    }
}

__global__ __launch_bounds__(THREADS, 2)
void lstm_hmma_kernel(const float* __restrict__ oldc, GateParams gp,
                      float* __restrict__ outh, float* __restrict__ outc)
{
    extern __shared__ char dyn_raw[];
    char* dyn = (char*)(((uintptr_t)dyn_raw + 1023) & ~(uintptr_t)1023);
    __shared__ float bias_sm[128];

    const int tid  = threadIdx.x;
    const int lane = tid & 31;
    const int warp = tid >> 5;
    const int wm   = warp >> 2;          // 0..1 : 64 m-rows each
    const int wn   = warp & 3;           // 0..3 : 32 n-cols each
    const int h0   = blockIdx.x * 32;    // 32 h-tiles of 32
    const int m0   = blockIdx.y * 128;   // 32 m-tiles

    if (tid < 128) bias_sm[tid] = gp.b[tid >> 5][h0 + (tid & 31)];

    const int colf4  = tid & 7;     // 16B block within 128B row
    const int rowgrp = tid >> 3;    // 0..31; handles rows rowgrp+32i

    const uint32_t sm_base = smem_u32(dyn);
    const uint32_t arow_b = (uint32_t)((wm * 64 + (lane & 15)) * 128) + ((lane >> 4) << 4);
    const uint32_t brow_b = (uint32_t)((wn * 32 + ((lane >> 4) << 3) + (lane & 7)) * 128) + (((lane >> 3) & 1) << 4);

    uint32_t tdst[4];
    #pragma unroll
    for (int i = 0; i < 4; i++)
        tdst[i] = sw128((uint32_t)((rowgrp + 32 * i) * 128 + colf4 * 16));

    // B tile rows: n = gate*32 + hh; row rowgrp+32i -> gate i, hh = rowgrp.
    auto issue_chunk = [&](int c, uint32_t bufsm) {
        const int seg = c >> 4;
        const int kc  = c & 15;
        const unsigned char* abase = g_scr + ((size_t)(seg * 4096 + m0 + rowgrp)) * 2048 + kc * 128 + colf4 * 16;
        const unsigned char* bbase = g_scr + ((size_t)(8192 + seg * 4096 + h0 + rowgrp)) * 2048 + kc * 128 + colf4 * 16;
        #pragma unroll
        for (int i = 0; i < 4; i++) {
            CP_ASYNC16(bufsm + tdst[i], abase + (size_t)i * 32 * 2048);
            CP_ASYNC16(bufsm + A_STAGE_BYTES + tdst[i], bbase + (size_t)i * 1024 * 2048);
        }
    };

    float acc[4][4][4];
    #pragma unroll
    for (int mt = 0; mt < 4; mt++)
        #pragma unroll
        for (int nt = 0; nt < 4; nt++)
            #pragma unroll
            for (int q = 0; q < 4; q++) acc[mt][nt][q] = 0.0f;

    #pragma unroll
    for (int p = 0; p < STAGES - 1; p++) {
        issue_chunk(p, sm_base + p * STAGE_BYTES);
        CP_COMMIT();
    }
    CP_WAIT(STAGES - 2);
    __syncthreads();

    int buf = 0;
    for (int c = 0; c < NCHUNK; c++) {
        int nc2 = c + STAGES - 1;
        if (nc2 < NCHUNK) {
            int nb = buf + STAGES - 1; if (nb >= STAGES) nb -= STAGES;
            issue_chunk(nc2, sm_base + nb * STAGE_BYTES);
        }
        CP_COMMIT();

        // compute 64-K chunk: 4 k16 steps
        {
            const uint32_t stA = sm_base + buf * STAGE_BYTES;
            const uint32_t stB = stA + A_STAGE_BYTES;
            #pragma unroll
            for (int ks = 0; ks < 4; ks++) {
                uint32_t ah[4][4], bb[4][2];
                #pragma unroll
                for (int mt = 0; mt < 4; mt++)
                    ldsm_x4(ah[mt], stA + sw128(arow_b + (uint32_t)(mt * 2048 + ks * 32)));
                #pragma unroll
                for (int nt2 = 0; nt2 < 2; nt2++) {
                    uint32_t r[4];
                    ldsm_x4(r, stB + sw128(brow_b + (uint32_t)(nt2 * 2048 + ks * 32)));
                    bb[nt2*2][0] = r[0]; bb[nt2*2][1] = r[1];
                    bb[nt2*2+1][0] = r[2]; bb[nt2*2+1][1] = r[3];
                }
                #pragma unroll
                for (int mt = 0; mt < 4; mt++)
                    #pragma unroll
                    for (int nt = 0; nt < 4; nt++)
                        mma_f16(acc[mt][nt], ah[mt], bb[nt]);
            }
        }

        CP_WAIT(STAGES - 2);
        __syncthreads();
        if (++buf == STAGES) buf = 0;
    }

    // ---- epilogue: accs -> smem transpose [n][m], then fused LSTM ----
    float* Csm = reinterpret_cast<float*>(dyn);   // [128][129] floats (66 KB < 97 KB)
    {
        const int gid = lane >> 2;
        const int tig = lane & 3;
        #pragma unroll
        for (int mt = 0; mt < 4; mt++)
            #pragma unroll
            for (int nt = 0; nt < 4; nt++) {
                int row = wm * 64 + mt * 16 + gid;
                int col = wn * 32 + nt * 8 + tig * 2;
                Csm[(col    ) * 129 + row    ] = acc[mt][nt][0];
                Csm[(col + 1) * 129 + row    ] = acc[mt][nt][1];
                Csm[(col    ) * 129 + row + 8] = acc[mt][nt][2];
                Csm[(col + 1) * 129 + row + 8] = acc[mt][nt][3];
            }
    }
    __syncthreads();

    #pragma unroll
    for (int it = 0; it < 16; it++) {
        int idx = tid + it * 256;           // 4096 = 128 m x 32 hh
        int hh = idx & 31;
        int m  = idx >> 5;
        float gi = Csm[( 0 + hh) * 129 + m] + bias_sm[ 0 + hh];
        float go = Csm[(32 + hh) * 129 + m] + bias_sm[32 + hh];
        float gf = Csm[(64 + hh) * 129 + m] + bias_sm[64 + hh];
        float gc = Csm[(96 + hh) * 129 + m] + bias_sm[96 + hh];
        size_t g = (size_t)(m0 + m) * 1024 + h0 + hh;
        float ig = fast_sig(gi);
        float og = fast_sig(go);
        float fg = fast_sig(gf);
        float ct = fast_tanh(gc);
        float nc = fg * oldc[g] + ig * ct;
        outh[g] = og * fast_tanh(nc);
        outc[g] = nc;
    }
}

extern "C" void kernel_launch(void* const* d_in, const int* in_sizes, int n_in,
                              void* d_out, int out_size)
{
    const float* incoming = (const float*)d_in[0];
    const float* old_h    = (const float*)d_in[1];
    const float* old_c    = (const float*)d_in[2];

    GateParams gp;
    gp.w[0] = (const float*)d_in[3];  gp.b[0] = (const float*)d_in[4];  gp.u[0] = (const float*)d_in[5];
    gp.w[1] = (const float*)d_in[6];  gp.b[1] = (const float*)d_in[7];  gp.u[1] = (const float*)d_in[8];
    gp.w[2] = (const float*)d_in[9];  gp.b[2] = (const float*)d_in[10]; gp.u[2] = (const float*)d_in[11];
    gp.w[3] = (const float*)d_in[12]; gp.b[3] = (const float*)d_in[13]; gp.u[3] = (const float*)d_in[14];

    float* out_h = (float*)d_out;
    float* out_c = out_h + (size_t)BATCHSZ * HID;

    convert_kernel<<<1024, 256>>>(incoming, old_h, gp);

    cudaFuncSetAttribute(lstm_hmma_kernel, cudaFuncAttributeMaxDynamicSharedMemorySize, DYN_BYTES);
    dim3 grid(HID / 32, BATCHSZ / 128);   // 32 x 32 = 1024 CTAs
    lstm_hmma_kernel<<<grid, THREADS, DYN_BYTES>>>(old_c, gp, out_h, out_c);
}